// round 15
// baseline (speedup 1.0000x reference)
#include <cuda_runtime.h>
#include <cuda_bf16.h>
#include <cstdint>

// Problem constants
namespace {
constexpr int Bn  = 512;
constexpr int Sn  = 64;
constexpr int En  = 768;
constexpr int Dn  = 256;
constexpr int BS  = Bn * Sn;     // 32768
constexpr int FIN = 1024;        // 2*D*(M-1)
}

// ---- scratch (device globals: allocation-free rule) ----
// All intermediates stored as bf16 hi/lo pairs (same bytes as fp32).
__device__ __align__(256) __nv_bfloat16 g_ph[3][(size_t)BS * Dn];  // proj hi
__device__ __align__(256) __nv_bfloat16 g_pl[3][(size_t)BS * Dn];  // proj lo
__device__ __align__(256) __nv_bfloat16 g_th[(size_t)BS * Dn];     // t hi
__device__ __align__(256) __nv_bfloat16 g_tl[(size_t)BS * Dn];     // t lo
__device__ __align__(256) __nv_bfloat16 g_aTh[2][(size_t)Bn * 4096];
__device__ __align__(256) __nv_bfloat16 g_aTl[2][(size_t)Bn * 4096];
__device__ __align__(256) __nv_bfloat16 g_oh[2][(size_t)Bn * 4096];
__device__ __align__(256) __nv_bfloat16 g_ol[2][(size_t)Bn * 4096];
__device__ __align__(256) __nv_bfloat16 g_Wh[3 * Dn * En];  // weight hi parts
__device__ __align__(256) __nv_bfloat16 g_Wl[3 * Dn * En];  // weight lo parts
__device__ __align__(256) __nv_bfloat16 g_Ch[Dn * Dn];      // corr^T hi [n][k]
__device__ __align__(256) __nv_bfloat16 g_Cl[Dn * Dn];      // corr^T lo
__device__ __align__(256) __nv_bfloat16 g_fh[(size_t)BS * FIN];  // fused hi
__device__ __align__(256) __nv_bfloat16 g_fl[(size_t)BS * FIN];  // fused lo
__device__ __align__(256) __nv_bfloat16 g_Wbh[64 * FIN];         // Wb hi
__device__ __align__(256) __nv_bfloat16 g_Wbl[64 * FIN];         // Wb lo

// ============================================================
// helpers (baseline PTX only)
// ============================================================
__device__ __forceinline__ uint32_t smem_u32(const void* p) {
    uint32_t a;
    asm("{ .reg .u64 t; cvta.to.shared.u64 t, %1; cvt.u32.u64 %0, t; }" : "=r"(a) : "l"(p));
    return a;
}
#define CP_ASYNC16(dst, src) \
    asm volatile("cp.async.cg.shared.global [%0], [%1], 16;" :: "r"(dst), "l"(src))
#define CP_COMMIT() asm volatile("cp.async.commit_group;" ::: "memory")
#define CP_WAIT0()  asm volatile("cp.async.wait_group 0;" ::: "memory")
#define CP_WAIT1()  asm volatile("cp.async.wait_group 1;" ::: "memory")

#define LDSM_X4(r0, r1, r2, r3, addr) \
    asm volatile("ldmatrix.sync.aligned.m8n8.x4.shared.b16 {%0,%1,%2,%3}, [%4];" \
                 : "=r"(r0), "=r"(r1), "=r"(r2), "=r"(r3) : "r"(addr))

#define LDSM_X4_T(r0, r1, r2, r3, addr) \
    asm volatile("ldmatrix.sync.aligned.m8n8.x4.trans.shared.b16 {%0,%1,%2,%3}, [%4];" \
                 : "=r"(r0), "=r"(r1), "=r"(r2), "=r"(r3) : "r"(addr))

__device__ __forceinline__ void mma_bf16(float* c, const uint32_t* a, const uint32_t* b) {
    asm volatile(
        "mma.sync.aligned.m16n8k16.row.col.f32.bf16.bf16.f32 "
        "{%0,%1,%2,%3}, {%4,%5,%6,%7}, {%8,%9}, {%0,%1,%2,%3};"
        : "+f"(c[0]), "+f"(c[1]), "+f"(c[2]), "+f"(c[3])
        : "r"(a[0]), "r"(a[1]), "r"(a[2]), "r"(a[3]), "r"(b[0]), "r"(b[1]));
}

__device__ __forceinline__ uint32_t pk_bf16x2(float lo, float hi) {
    uint32_t r;
    asm("cvt.rn.bf16x2.f32 %0, %1, %2;" : "=r"(r) : "f"(hi), "f"(lo));
    return r;
}
__device__ __forceinline__ float bf16bits_f(uint32_t b16) { return __uint_as_float(b16 << 16); }

__device__ __forceinline__ void split4(float4 v, uint2& hi, uint2& lo) {
    uint32_t h01 = pk_bf16x2(v.x, v.y);
    uint32_t h23 = pk_bf16x2(v.z, v.w);
    float rx = v.x - bf16bits_f(h01 & 0xffffu);
    float ry = v.y - bf16bits_f(h01 >> 16);
    float rz = v.z - bf16bits_f(h23 & 0xffffu);
    float rw = v.w - bf16bits_f(h23 >> 16);
    hi.x = h01; hi.y = h23;
    lo.x = pk_bf16x2(rx, ry);
    lo.y = pk_bf16x2(rz, rw);
}

__device__ __forceinline__ void split1(float v, __nv_bfloat16* hp, __nv_bfloat16* lp) {
    __nv_bfloat16 h = __float2bfloat16(v);
    *hp = h;
    *lp = __float2bfloat16(v - __bfloat162float(h));
}

// split a pair and store hi/lo uint32s
__device__ __forceinline__ void split2_store(float v0, float v1,
                                             __nv_bfloat16* ph, __nv_bfloat16* pl) {
    uint32_t hh = pk_bf16x2(v0, v1);
    float q0 = v0 - bf16bits_f(hh & 0xffffu);
    float q1 = v1 - bf16bits_f(hh >> 16);
    *(uint32_t*)ph = hh;
    *(uint32_t*)pl = pk_bf16x2(q0, q1);
}

// ============================================================
// Kernel B: convert weights fp32 -> bf16 hi/lo (3 modalities)
// ============================================================
__global__ __launch_bounds__(256) void wconv_kernel(
    const float* __restrict__ W0, const float* __restrict__ W1, const float* __restrict__ W2)
{
    const int m = blockIdx.y;
    const float* W = (m == 0) ? W0 : (m == 1) ? W1 : W2;
    const size_t base = (size_t)m * Dn * En;
    int idx = (blockIdx.x * 256 + threadIdx.x) * 4;
    float4 v = *(const float4*)(W + idx);
    uint2 hi, lo;
    split4(v, hi, lo);
    *(uint2*)(g_Wh + base + idx) = hi;
    *(uint2*)(g_Wl + base + idx) = lo;
}

__global__ __launch_bounds__(256) void wbconv_kernel(const float* __restrict__ Wb)
{
    int idx = (blockIdx.x * 256 + threadIdx.x) * 4;
    float4 v = *(const float4*)(Wb + idx);
    uint2 hi, lo;
    split4(v, hi, lo);
    *(uint2*)(g_Wbh + idx) = hi;
    *(uint2*)(g_Wbl + idx) = lo;
}

// corr^T split: g_Ch/g_Cl[n][k] = split(corr[k][n]); 256x256
__global__ __launch_bounds__(256) void cprep_kernel(const float* __restrict__ corr)
{
    __shared__ float tile[32][33];
    const int n0 = (blockIdx.x & 7) * 32;
    const int k0 = (blockIdx.x >> 3) * 32;
    const int tr = threadIdx.x >> 5, tc = threadIdx.x & 31;
    for (int r = tr; r < 32; r += 8)
        tile[r][tc] = corr[(size_t)(k0 + r) * Dn + n0 + tc];
    __syncthreads();
    for (int r = tr; r < 32; r += 8) {
        float v = tile[tc][r];
        split1(v, &g_Ch[(size_t)(n0 + r) * Dn + k0 + tc], &g_Cl[(size_t)(n0 + r) * Dn + k0 + tc]);
    }
}

// ============================================================
// Kernel C: HMMA projection GEMM, 256 threads / 8 warps (2M x 4N),
// warp tile 64x64, 3-stage cp.async pipeline. K=768, z in {0,1,2}.
// Outputs bf16 hi/lo. z==0 additionally computes t = tile @ corrT^T.
// ============================================================
namespace {
constexpr int NCHUNK = En / 32;                 // 24
constexpr uint32_t SZ_A  = 128 * 80;            // 10240
constexpr uint32_t SZ_B  = 256 * 80;            // 20480
constexpr uint32_t STAGE = 2 * SZ_A + 2 * SZ_B; // 61440
constexpr uint32_t TD_HI = 0;                   // 8 chunks x 10240
constexpr uint32_t TD_LO = 81920;
constexpr uint32_t TD_B  = 163840;              // 2 stages x 20480
constexpr uint32_t SMEM_PROJ = 204800;
}

__global__ __launch_bounds__(256, 1)
void proj_mma_kernel(const float* __restrict__ L0, const float* __restrict__ L1,
                     const float* __restrict__ L2,
                     const float* __restrict__ P0, const float* __restrict__ P1,
                     const float* __restrict__ P2)
{
    extern __shared__ char dsm[];
    const uint32_t sb = smem_u32(dsm);
    const int tid  = threadIdx.x;
    const int lane = tid & 31;
    const int wid  = tid >> 5;
    const int wm   = wid & 1;
    const int wn   = wid >> 1;
    const int z    = blockIdx.y;
    const int row0 = blockIdx.x * 128;

    const float* A = (z == 1) ? L1 : (z == 2) ? L2 : L0;
    const __nv_bfloat16* Wh = g_Wh + (size_t)z * Dn * En;
    const __nv_bfloat16* Wl = g_Wl + (size_t)z * Dn * En;

    const int bn   = tid >> 2;
    const int bseg = tid & 3;
    const int ar = tid >> 1;
    const int ah = tid & 1;

    float4 af[4];

    const uint32_t aOff = (uint32_t)((wm * 64 + (lane & 15)) * 80 + (lane >> 4) * 16);
    const uint32_t bOff = (uint32_t)((wn * 64 + (lane & 7) + ((lane >> 4) << 3)) * 80 +
                                     ((lane >> 3) & 1) * 16);

    float c[4][8][4] = {};

    {
#pragma unroll
        for (int pc = 0; pc < 2; ++pc) {
            const uint32_t bhi = sb + pc * STAGE + 2 * SZ_A;
            const uint32_t blo = bhi + SZ_B;
            const int k0 = pc * 32;
#pragma unroll
            for (int r = 0; r < 4; ++r) {
                int row = bn + r * 64;
                CP_ASYNC16(bhi + row * 80 + bseg * 16, Wh + (size_t)row * 768 + k0 + bseg * 8);
                CP_ASYNC16(blo + row * 80 + bseg * 16, Wl + (size_t)row * 768 + k0 + bseg * 8);
            }
            CP_COMMIT();
        }
        const float* p = A + (size_t)(row0 + ar) * 768 + ah * 16;
        af[0] = *(const float4*)(p);
        af[1] = *(const float4*)(p + 4);
        af[2] = *(const float4*)(p + 8);
        af[3] = *(const float4*)(p + 12);
    }

    int st = 0;
#pragma unroll 1
    for (int ch = 0; ch < NCHUNK; ++ch) {
        {
            char* ahi = dsm + st * STAGE;
            char* alo = ahi + SZ_A;
            const uint32_t off = (uint32_t)(ar * 80 + ah * 32);
#pragma unroll
            for (int q = 0; q < 4; ++q) {
                uint2 hi, lo;
                split4(af[q], hi, lo);
                *(uint2*)(ahi + off + q * 8) = hi;
                *(uint2*)(alo + off + q * 8) = lo;
            }
        }
        if (ch < NCHUNK - 1) {
            const float* p = A + (size_t)(row0 + ar) * 768 + (ch + 1) * 32 + ah * 16;
            af[0] = *(const float4*)(p);
            af[1] = *(const float4*)(p + 4);
            af[2] = *(const float4*)(p + 8);
            af[3] = *(const float4*)(p + 12);
        }
        if (ch < NCHUNK - 1) { CP_WAIT1(); } else { CP_WAIT0(); }
        __syncthreads();
        if (ch + 2 < NCHUNK) {
            const int st2 = (st >= 1) ? st - 1 : st + 2;
            const int k2 = (ch + 2) * 32;
            const uint32_t bhi = sb + st2 * STAGE + 2 * SZ_A;
            const uint32_t blo = bhi + SZ_B;
#pragma unroll
            for (int r = 0; r < 4; ++r) {
                int row = bn + r * 64;
                CP_ASYNC16(bhi + row * 80 + bseg * 16, Wh + (size_t)row * 768 + k2 + bseg * 8);
                CP_ASYNC16(blo + row * 80 + bseg * 16, Wl + (size_t)row * 768 + k2 + bseg * 8);
            }
            CP_COMMIT();
        }
        {
            const uint32_t aHiB = sb + st * STAGE + aOff;
            const uint32_t aLoB = aHiB + SZ_A;
            const uint32_t bHiB = sb + st * STAGE + 2 * SZ_A + bOff;
            const uint32_t bLoB = bHiB + SZ_B;
#pragma unroll
            for (int ks = 0; ks < 2; ++ks) {
                const uint32_t ko = ks * 32;
                uint32_t ahr[4][4], bb[8][2];
#pragma unroll
                for (int i = 0; i < 4; ++i)
                    LDSM_X4(ahr[i][0], ahr[i][1], ahr[i][2], ahr[i][3], aHiB + ko + i * 1280);
#pragma unroll
                for (int j2 = 0; j2 < 4; ++j2)
                    LDSM_X4(bb[2 * j2][0], bb[2 * j2][1], bb[2 * j2 + 1][0], bb[2 * j2 + 1][1],
                            bHiB + ko + j2 * 1280);
#pragma unroll
                for (int i = 0; i < 4; ++i)
#pragma unroll
                    for (int j = 0; j < 8; ++j) mma_bf16(c[i][j], ahr[i], bb[j]);

                uint32_t alr[4][4];
#pragma unroll
                for (int i = 0; i < 4; ++i)
                    LDSM_X4(alr[i][0], alr[i][1], alr[i][2], alr[i][3], aLoB + ko + i * 1280);
#pragma unroll
                for (int i = 0; i < 4; ++i)
#pragma unroll
                    for (int j = 0; j < 8; ++j) mma_bf16(c[i][j], alr[i], bb[j]);

#pragma unroll
                for (int j2 = 0; j2 < 4; ++j2)
                    LDSM_X4(bb[2 * j2][0], bb[2 * j2][1], bb[2 * j2 + 1][0], bb[2 * j2 + 1][1],
                            bLoB + ko + j2 * 1280);
#pragma unroll
                for (int i = 0; i < 4; ++i)
#pragma unroll
                    for (int j = 0; j < 8; ++j) mma_bf16(c[i][j], ahr[i], bb[j]);
            }
        }
        st = (st == 2) ? 0 : st + 1;
    }

    const float* bias = (z == 0) ? P0 : (z == 1) ? P1 : P2;
    const int colBase = wn * 64 + (lane & 3) * 2;
    const int rowBase = row0 + wm * 64 + (lane >> 2);

    if (z != 0) {
        __nv_bfloat16* Ph = g_ph[z];
        __nv_bfloat16* Pl = g_pl[z];
#pragma unroll
        for (int j = 0; j < 8; ++j) {
            const int col = colBase + j * 8;
            const float b0 = bias[col], b1 = bias[col + 1];
#pragma unroll
            for (int i = 0; i < 4; ++i) {
                const int r = rowBase + i * 16;
                split2_store(c[i][j][0] + b0, c[i][j][1] + b1,
                             Ph + (size_t)r * 256 + col, Pl + (size_t)r * 256 + col);
                split2_store(c[i][j][2] + b0, c[i][j][3] + b1,
                             Ph + (size_t)(r + 8) * 256 + col, Pl + (size_t)(r + 8) * 256 + col);
            }
        }
        return;
    }

    // ================= z==0: write g_ph[0]/g_pl[0] + fused tmat =================
    __syncthreads();   // all main-loop smem reads finished
    {
        const int lr = wm * 64 + (lane >> 2);
#pragma unroll
        for (int j = 0; j < 8; ++j) {
            const int col = colBase + j * 8;
            const float b0 = bias[col], b1 = bias[col + 1];
            const int kc = col >> 5, c32 = col & 31;
#pragma unroll
            for (int i = 0; i < 4; ++i) {
#pragma unroll
                for (int half = 0; half < 2; ++half) {
                    const int r = lr + i * 16 + half * 8;
                    float v0 = c[i][j][half * 2 + 0] + b0;
                    float v1 = c[i][j][half * 2 + 1] + b1;
                    uint32_t hh = pk_bf16x2(v0, v1);
                    float q0 = v0 - bf16bits_f(hh & 0xffffu);
                    float q1 = v1 - bf16bits_f(hh >> 16);
                    uint32_t ll = pk_bf16x2(q0, q1);
                    *(uint32_t*)(dsm + TD_HI + kc * 10240 + r * 80 + c32 * 2) = hh;
                    *(uint32_t*)(dsm + TD_LO + kc * 10240 + r * 80 + c32 * 2) = ll;
                    *(uint32_t*)(g_ph[0] + (size_t)(row0 + r) * 256 + col) = hh;
                    *(uint32_t*)(g_pl[0] + (size_t)(row0 + r) * 256 + col) = ll;
                }
            }
        }
    }
    const int tbrow = tid >> 1;
    const int tbs   = (tid & 1) * 2;
    {
        const uint32_t bhi = sb + TD_B;
        const uint32_t blo = bhi + 10240;
#pragma unroll
        for (int s = 0; s < 2; ++s) {
            int seg = tbs + s;
            CP_ASYNC16(bhi + tbrow * 80 + seg * 16, g_Ch + (size_t)tbrow * 256 + seg * 8);
            CP_ASYNC16(blo + tbrow * 80 + seg * 16, g_Cl + (size_t)tbrow * 256 + seg * 8);
        }
        CP_COMMIT();
    }

    const uint32_t a2off = (uint32_t)((wm * 64 + (lane & 15)) * 80 + (lane >> 4) * 16);
    const uint32_t b2off = (uint32_t)((wn * 32 + (lane & 7) + ((lane >> 4) << 3)) * 80 +
                                      ((lane >> 3) & 1) * 16);
    float c2[4][4][4] = {};

#pragma unroll 1
    for (int it = 0; it < 16; ++it) {
        const int stg = it & 1;
        const int nh = it >> 3, kc = it & 7;
        CP_WAIT0();
        __syncthreads();
        if (it < 15) {
            const int nh1 = (it + 1) >> 3, kc1 = (it + 1) & 7;
            const uint32_t bhi = sb + TD_B + (stg ^ 1) * 20480;
            const uint32_t blo = bhi + 10240;
#pragma unroll
            for (int s = 0; s < 2; ++s) {
                int seg = tbs + s;
                CP_ASYNC16(bhi + tbrow * 80 + seg * 16,
                           g_Ch + (size_t)(nh1 * 128 + tbrow) * 256 + kc1 * 32 + seg * 8);
                CP_ASYNC16(blo + tbrow * 80 + seg * 16,
                           g_Cl + (size_t)(nh1 * 128 + tbrow) * 256 + kc1 * 32 + seg * 8);
            }
            CP_COMMIT();
        }
        {
            const uint32_t aHiB = sb + TD_HI + kc * 10240 + a2off;
            const uint32_t aLoB = aHiB + (TD_LO - TD_HI);
            const uint32_t bHiB = sb + TD_B + stg * 20480 + b2off;
            const uint32_t bLoB = bHiB + 10240;
#pragma unroll
            for (int ks = 0; ks < 2; ++ks) {
                const uint32_t ko = ks * 32;
                uint32_t ahr[4][4], bb[4][2];
#pragma unroll
                for (int i = 0; i < 4; ++i)
                    LDSM_X4(ahr[i][0], ahr[i][1], ahr[i][2], ahr[i][3], aHiB + ko + i * 1280);
#pragma unroll
                for (int j2 = 0; j2 < 2; ++j2)
                    LDSM_X4(bb[2 * j2][0], bb[2 * j2][1], bb[2 * j2 + 1][0], bb[2 * j2 + 1][1],
                            bHiB + ko + j2 * 1280);
#pragma unroll
                for (int i = 0; i < 4; ++i)
#pragma unroll
                    for (int j = 0; j < 4; ++j) mma_bf16(c2[i][j], ahr[i], bb[j]);

                uint32_t alr[4][4];
#pragma unroll
                for (int i = 0; i < 4; ++i)
                    LDSM_X4(alr[i][0], alr[i][1], alr[i][2], alr[i][3], aLoB + ko + i * 1280);
#pragma unroll
                for (int i = 0; i < 4; ++i)
#pragma unroll
                    for (int j = 0; j < 4; ++j) mma_bf16(c2[i][j], alr[i], bb[j]);

#pragma unroll
                for (int j2 = 0; j2 < 2; ++j2)
                    LDSM_X4(bb[2 * j2][0], bb[2 * j2][1], bb[2 * j2 + 1][0], bb[2 * j2 + 1][1],
                            bLoB + ko + j2 * 1280);
#pragma unroll
                for (int i = 0; i < 4; ++i)
#pragma unroll
                    for (int j = 0; j < 4; ++j) mma_bf16(c2[i][j], ahr[i], bb[j]);
            }
        }
        if (kc == 7) {
            const int colB2 = nh * 128 + wn * 32 + (lane & 3) * 2;
#pragma unroll
            for (int j = 0; j < 4; ++j) {
                const int col = colB2 + j * 8;
#pragma unroll
                for (int i = 0; i < 4; ++i) {
                    const int r = rowBase + i * 16;
                    split2_store(c2[i][j][0], c2[i][j][1],
                                 g_th + (size_t)r * 256 + col, g_tl + (size_t)r * 256 + col);
                    split2_store(c2[i][j][2], c2[i][j][3],
                                 g_th + (size_t)(r + 8) * 256 + col, g_tl + (size_t)(r + 8) * 256 + col);
                }
            }
#pragma unroll
            for (int i = 0; i < 4; ++i)
#pragma unroll
                for (int j = 0; j < 4; ++j)
#pragma unroll
                    for (int q = 0; q < 4; ++q) c2[i][j][q] = 0.f;
        }
    }
}

// ============================================================
// Kernel 3 (HMMA): per (b,p): cc = T @ O^T via mma.sync; operands
// cp.async'd directly (pre-split bf16 hi/lo in gmem). Dual softmax,
// outputs written as bf16 hi/lo.
// ============================================================
namespace {
constexpr uint32_t CS_TH = 0;                      // 64 x 144B
constexpr uint32_t CS_TL = 64 * 144;               // 9216
constexpr uint32_t CS_OH = 2 * 64 * 144;           // 18432
constexpr uint32_t CS_OL = 3 * 64 * 144;           // 27648
constexpr uint32_t CS_SC = 4 * 64 * 144;           // 36864 (floats [64][65])
constexpr uint32_t SMEM_CS = CS_SC + 64 * 65 * 4;  // 53504
}

__global__ __launch_bounds__(256) void ccsm_mma_kernel()
{
    extern __shared__ char dsm[];
    const uint32_t sb = smem_u32(dsm);
    const int b = blockIdx.x;
    const int p = blockIdx.y;

    const int tid = threadIdx.x;
    const int lane = tid & 31;
    const int wid  = tid >> 5;
    const int wm   = wid & 1;
    const int wn   = wid >> 1;

    const size_t rowOff = (size_t)(b * 64) * 256;
    const __nv_bfloat16* Oh = g_ph[p + 1];
    const __nv_bfloat16* Ol = g_pl[p + 1];

    // cp.async staging map: row=tid>>2, segs (tid&3)*2, +1
    const int cr = tid >> 2;
    const int cs0 = (tid & 3) * 2;

    const uint32_t aBase = sb + CS_TH +
        (uint32_t)((wm * 32 + (lane & 15)) * 144 + (lane >> 4) * 16);
    const uint32_t bBase = sb + CS_OH +
        (uint32_t)((wn * 16 + (lane & 7) + ((lane >> 4) << 3)) * 144 + ((lane >> 3) & 1) * 16);

    float c[2][2][4] = {};

#pragma unroll 1
    for (int kc = 0; kc < 4; ++kc) {
        // ---- stage T/O chunk via cp.async (no conversion work) ----
#pragma unroll
        for (int s = 0; s < 2; ++s) {
            const int seg = cs0 + s;
            const size_t src = rowOff + (size_t)cr * 256 + kc * 64 + seg * 8;
            const uint32_t d = (uint32_t)(cr * 144 + seg * 16);
            CP_ASYNC16(sb + CS_TH + d, g_th + src);
            CP_ASYNC16(sb + CS_TL + d, g_tl + src);
            CP_ASYNC16(sb + CS_OH + d, Oh + src);
            CP_ASYNC16(sb + CS_OL + d, Ol + src);
        }
        CP_COMMIT();
        CP_WAIT0();
        __syncthreads();
#pragma unroll
        for (int ks = 0; ks < 4; ++ks) {
            const uint32_t ko = (uint32_t)(ks * 32);
            uint32_t ahr[2][4], bb[2][2];
#pragma unroll
            for (int i = 0; i < 2; ++i)
                LDSM_X4(ahr[i][0], ahr[i][1], ahr[i][2], ahr[i][3], aBase + ko + i * 16 * 144);
            LDSM_X4(bb[0][0], bb[0][1], bb[1][0], bb[1][1], bBase + ko);
#pragma unroll
            for (int i = 0; i < 2; ++i)
#pragma unroll
                for (int j = 0; j < 2; ++j) mma_bf16(c[i][j], ahr[i], bb[j]);

            uint32_t alr[2][4];
#pragma unroll
            for (int i = 0; i < 2; ++i)
                LDSM_X4(alr[i][0], alr[i][1], alr[i][2], alr[i][3],
                        aBase + (CS_TL - CS_TH) + ko + i * 16 * 144);
#pragma unroll
            for (int i = 0; i < 2; ++i)
#pragma unroll
                for (int j = 0; j < 2; ++j) mma_bf16(c[i][j], alr[i], bb[j]);

            uint32_t bl[2][2];
            LDSM_X4(bl[0][0], bl[0][1], bl[1][0], bl[1][1], bBase + (CS_OL - CS_OH) + ko);
#pragma unroll
            for (int i = 0; i < 2; ++i)
#pragma unroll
                for (int j = 0; j < 2; ++j) mma_bf16(c[i][j], ahr[i], bl[j]);
        }
        __syncthreads();
    }

    float* sc = (float*)(dsm + CS_SC);
    {
        const int rowB = wm * 32 + (lane >> 2);
        const int colB = wn * 16 + (lane & 3) * 2;
#pragma unroll
        for (int i = 0; i < 2; ++i)
#pragma unroll
            for (int j = 0; j < 2; ++j) {
                sc[(rowB + i * 16)     * 65 + colB + j * 8]     = c[i][j][0];
                sc[(rowB + i * 16)     * 65 + colB + j * 8 + 1] = c[i][j][1];
                sc[(rowB + i * 16 + 8) * 65 + colB + j * 8]     = c[i][j][2];
                sc[(rowB + i * 16 + 8) * 65 + colB + j * 8 + 1] = c[i][j][3];
            }
    }
    __syncthreads();

    const int warp = wid, lane2 = lane;
    const size_t mOff = (size_t)b * 4096;

    for (int r = warp; r < 64; r += 8) {
        float x0 = sc[r * 65 + lane2], x1 = sc[r * 65 + lane2 + 32];
        float mx = fmaxf(x0, x1);
#pragma unroll
        for (int o = 16; o > 0; o >>= 1) mx = fmaxf(mx, __shfl_xor_sync(0xffffffffu, mx, o));
        float e0 = __expf(x0 - mx), e1 = __expf(x1 - mx);
        float s = e0 + e1;
#pragma unroll
        for (int o = 16; o > 0; o >>= 1) s += __shfl_xor_sync(0xffffffffu, s, o);
        float inv = 1.0f / s;
        split1(e0 * inv, &g_oh[p][mOff + r * 64 + lane2],      &g_ol[p][mOff + r * 64 + lane2]);
        split1(e1 * inv, &g_oh[p][mOff + r * 64 + lane2 + 32], &g_ol[p][mOff + r * 64 + lane2 + 32]);
    }
    for (int cix = warp; cix < 64; cix += 8) {
        float x0 = sc[lane2 * 65 + cix], x1 = sc[(lane2 + 32) * 65 + cix];
        float mx = fmaxf(x0, x1);
#pragma unroll
        for (int o = 16; o > 0; o >>= 1) mx = fmaxf(mx, __shfl_xor_sync(0xffffffffu, mx, o));
        float e0 = __expf(x0 - mx), e1 = __expf(x1 - mx);
        float s = e0 + e1;
#pragma unroll
        for (int o = 16; o > 0; o >>= 1) s += __shfl_xor_sync(0xffffffffu, s, o);
        float inv = 1.0f / s;
        split1(e0 * inv, &g_aTh[p][mOff + cix * 64 + lane2],      &g_aTl[p][mOff + cix * 64 + lane2]);
        split1(e1 * inv, &g_aTh[p][mOff + cix * 64 + lane2 + 32], &g_aTl[p][mOff + cix * 64 + lane2 + 32]);
    }
}

// ============================================================
// Kernel 4 (HMMA): att GEMM + residual -> fused bf16 hi/lo.
// All operands cp.async'd (pre-split hi/lo in gmem).
// ============================================================
namespace {
constexpr uint32_t AT_A_H = 0;                       // 64 rows x 144B
constexpr uint32_t AT_A_L = 64 * 144;                // 9216
constexpr uint32_t AT_X_H = 2 * 64 * 144;            // 18432; 64 rows x 528B
constexpr uint32_t AT_X_L = AT_X_H + 64 * 528;       // 52224
constexpr uint32_t SMEM_AT = AT_X_L + 64 * 528;      // 86016
}

__global__ __launch_bounds__(256)
void attfuse_mma_kernel()
{
    extern __shared__ char dsm[];
    const uint32_t sb = smem_u32(dsm);
    const int b    = blockIdx.x;
    const int p    = blockIdx.y >> 1;
    const int side = blockIdx.y & 1;
    const int tid  = threadIdx.x;
    const int lane = tid & 31;
    const int wid  = tid >> 5;
    const int wm   = wid & 1;
    const int wn   = wid >> 1;

    const __nv_bfloat16* Mh = (side == 0) ? g_aTh[p] : g_oh[p];
    const __nv_bfloat16* Ml = (side == 0) ? g_aTl[p] : g_ol[p];
    const __nv_bfloat16* Xh = (side == 0) ? g_ph[0] : g_ph[p + 1];
    const __nv_bfloat16* Xl = (side == 0) ? g_pl[0] : g_pl[p + 1];
    const size_t mOff = (size_t)b * 4096;
    const size_t xOff = (size_t)(b * 64) * 256;

    // ---- stage A (Mat) via cp.async: 64 rows x 128B x2 ----
    {
        const int r = tid >> 2;
        const int s0 = (tid & 3) * 2;
#pragma unroll
        for (int s = 0; s < 2; ++s) {
            const int seg = s0 + s;
            const uint32_t d = (uint32_t)(r * 144 + seg * 16);
            CP_ASYNC16(sb + AT_A_H + d, Mh + mOff + r * 64 + seg * 8);
            CP_ASYNC16(sb + AT_A_L + d, Ml + mOff + r * 64 + seg * 8);
        }
    }
    // ---- stage X via cp.async: 64 rows x 512B x2 ----
    {
        const int r = tid >> 2;
        const int s0 = (tid & 3) * 8;
#pragma unroll
        for (int s = 0; s < 8; ++s) {
            const int seg = s0 + s;
            const uint32_t d = (uint32_t)(r * 528 + seg * 16);
            CP_ASYNC16(sb + AT_X_H + d, Xh + xOff + (size_t)r * 256 + seg * 8);
            CP_ASYNC16(sb + AT_X_L + d, Xl + xOff + (size_t)r * 256 + seg * 8);
        }
    }
    CP_COMMIT();
    CP_WAIT0();
    __syncthreads();

    const uint32_t aHiB = sb + AT_A_H + (uint32_t)((wm * 32 + (lane & 15)) * 144 + (lane >> 4) * 16);
    const uint32_t aLoB = aHiB + (AT_A_L - AT_A_H);
    const uint32_t bHiB = sb + AT_X_H + (uint32_t)((lane & 15) * 528 + (wn * 64 + (lane >> 4) * 8) * 2);
    const uint32_t bLoB = bHiB + (AT_X_L - AT_X_H);

    float c[2][8][4] = {};

#pragma unroll 1
    for (int ks = 0; ks < 4; ++ks) {
        const uint32_t ak = (uint32_t)(ks * 32);
        const uint32_t bk = (uint32_t)(ks * 16 * 528);
        uint32_t ahr[2][4], bb[8][2];
#pragma unroll
        for (int i = 0; i < 2; ++i)
            LDSM_X4(ahr[i][0], ahr[i][1], ahr[i][2], ahr[i][3], aHiB + ak + i * 16 * 144);
#pragma unroll
        for (int j2 = 0; j2 < 4; ++j2)
            LDSM_X4_T(bb[2 * j2][0], bb[2 * j2][1], bb[2 * j2 + 1][0], bb[2 * j2 + 1][1],
                      bHiB + bk + j2 * 32);
#pragma unroll
        for (int i = 0; i < 2; ++i)
#pragma unroll
            for (int j = 0; j < 8; ++j) mma_bf16(c[i][j], ahr[i], bb[j]);

        uint32_t alr[2][4];
#pragma unroll
        for (int i = 0; i < 2; ++i)
            LDSM_X4(alr[i][0], alr[i][1], alr[i][2], alr[i][3], aLoB + ak + i * 16 * 144);
#pragma unroll
        for (int i = 0; i < 2; ++i)
#pragma unroll
            for (int j = 0; j < 8; ++j) mma_bf16(c[i][j], alr[i], bb[j]);

#pragma unroll
        for (int j2 = 0; j2 < 4; ++j2)
            LDSM_X4_T(bb[2 * j2][0], bb[2 * j2][1], bb[2 * j2 + 1][0], bb[2 * j2 + 1][1],
                      bLoB + bk + j2 * 32);
#pragma unroll
        for (int i = 0; i < 2; ++i)
#pragma unroll
            for (int j = 0; j < 8; ++j) mma_bf16(c[i][j], ahr[i], bb[j]);
    }

    const char* xhp = dsm + AT_X_H;
    const char* xlp = dsm + AT_X_L;
    const int rowBase = wm * 32 + (lane >> 2);
    const int colBase = wn * 64 + (lane & 3) * 2;
    const size_t dstBase = (size_t)(b * 64) * FIN + p * 512 + side * 256;
#pragma unroll
    for (int i = 0; i < 2; ++i) {
#pragma unroll
        for (int j = 0; j < 8; ++j) {
            const int col = colBase + j * 8;
#pragma unroll
            for (int half = 0; half < 2; ++half) {
                const int r = rowBase + i * 16 + half * 8;
                uint32_t rh = *(const uint32_t*)(xhp + r * 528 + col * 2);
                uint32_t rl = *(const uint32_t*)(xlp + r * 528 + col * 2);
                float res0 = bf16bits_f(rh & 0xffffu) + bf16bits_f(rl & 0xffffu);
                float res1 = bf16bits_f(rh >> 16)     + bf16bits_f(rl >> 16);
                float v0 = c[i][j][half * 2 + 0] + res0;
                float v1 = c[i][j][half * 2 + 1] + res1;
                uint32_t hh = pk_bf16x2(v0, v1);
                float q0 = v0 - bf16bits_f(hh & 0xffffu);
                float q1 = v1 - bf16bits_f(hh >> 16);
                uint32_t ll = pk_bf16x2(q0, q1);
                size_t e = dstBase + (size_t)r * FIN + col;
                *(uint32_t*)(g_fh + e) = hh;
                *(uint32_t*)(g_fl + e) = ll;
            }
        }
    }
}

// ============================================================
// Kernel 5: HMMA final: h = fused @ Wb^T + bb; LayerNorm(64); ReLU
// ============================================================
namespace {
constexpr int FNCH = FIN / 32;                    // 32
constexpr uint32_t F_SZ_A = 128 * 80;             // 10240
constexpr uint32_t F_SZ_B = 64 * 80;              // 5120
constexpr uint32_t F_STAGE = 2 * F_SZ_A + 2 * F_SZ_B;  // 30720
constexpr uint32_t SMEM_FIN = 2 * F_STAGE;        // 61440
}

__global__ __launch_bounds__(256, 1)
void final_mma_kernel(const float* __restrict__ bbv,
                      const float* __restrict__ gamma, const float* __restrict__ beta,
                      float* __restrict__ out)
{
    extern __shared__ char dsm[];
    const uint32_t sb = smem_u32(dsm);
    const int tid  = threadIdx.x;
    const int lane = tid & 31;
    const int wid  = tid >> 5;
    const int wm   = wid & 3;
    const int wn   = wid >> 2;
    const int row0 = blockIdx.x * 128;

    const int ar = tid >> 1, as0 = (tid & 1) * 2;
    const int bn = tid >> 2, bs = tid & 3;

    const uint32_t aOff = (uint32_t)((wm * 32 + (lane & 15)) * 80 + (lane >> 4) * 16);
    const uint32_t bOff = (uint32_t)((wn * 32 + (lane & 7) + ((lane >> 4) << 3)) * 80 +
                                     ((lane >> 3) & 1) * 16);

    float c[2][4][4] = {};

    {
        const uint32_t ahi = sb, alo = sb + F_SZ_A;
        const uint32_t bhi = sb + 2 * F_SZ_A, blo = bhi + F_SZ_B;
#pragma unroll
        for (int q = 0; q < 2; ++q) {
            int seg = as0 + q;
            CP_ASYNC16(ahi + ar * 80 + seg * 16, g_fh + (size_t)(row0 + ar) * FIN + seg * 8);
            CP_ASYNC16(alo + ar * 80 + seg * 16, g_fl + (size_t)(row0 + ar) * FIN + seg * 8);
        }
        CP_ASYNC16(bhi + bn * 80 + bs * 16, g_Wbh + (size_t)bn * FIN + bs * 8);
        CP_ASYNC16(blo + bn * 80 + bs * 16, g_Wbl + (size_t)bn * FIN + bs * 8);
        CP_COMMIT();
    }

#pragma unroll 1
    for (int ch = 0; ch < FNCH; ++ch) {
        const int st = ch & 1;
        CP_WAIT0();
        __syncthreads();
        if (ch < FNCH - 1) {
            const int k1 = (ch + 1) * 32;
            const uint32_t base = sb + (st ^ 1) * F_STAGE;
            const uint32_t ahi = base, alo = base + F_SZ_A;
            const uint32_t bhi = base + 2 * F_SZ_A, blo = bhi + F_SZ_B;
#pragma unroll
            for (int q = 0; q < 2; ++q) {
                int seg = as0 + q;
                CP_ASYNC16(ahi + ar * 80 + seg * 16, g_fh + (size_t)(row0 + ar) * FIN + k1 + seg * 8);
                CP_ASYNC16(alo + ar * 80 + seg * 16, g_fl + (size_t)(row0 + ar) * FIN + k1 + seg * 8);
            }
            CP_ASYNC16(bhi + bn * 80 + bs * 16, g_Wbh + (size_t)bn * FIN + k1 + bs * 8);
            CP_ASYNC16(blo + bn * 80 + bs * 16, g_Wbl + (size_t)bn * FIN + k1 + bs * 8);
            CP_COMMIT();
        }
        {
            const uint32_t aHiB = sb + st * F_STAGE + aOff;
            const uint32_t aLoB = aHiB + F_SZ_A;
            const uint32_t bHiB = sb + st * F_STAGE + 2 * F_SZ_A + bOff;
            const uint32_t bLoB = bHiB + F_SZ_B;
#pragma unroll
            for (int ks = 0; ks < 2; ++ks) {
                const uint32_t ko = ks * 32;
                uint32_t ahr[2][4], bb[4][2];
#pragma unroll
                for (int i = 0; i < 2; ++i)
                    LDSM_X4(ahr[i][0], ahr[i][1], ahr[i][2], ahr[i][3], aHiB + ko + i * 1280);
#pragma unroll
                for (int j2 = 0; j2 < 2; ++j2)
                    LDSM_X4(bb[2 * j2][0], bb[2 * j2][1], bb[2 * j2 + 1][0], bb[2 * j2 + 1][1],
                            bHiB + ko + j2 * 1280);
#pragma unroll
                for (int i = 0; i < 2; ++i)
#pragma unroll
                    for (int j = 0; j < 4; ++j) mma_bf16(c[i][j], ahr[i], bb[j]);

                uint32_t alr[2][4];
#pragma unroll
                for (int i = 0; i < 2; ++i)
                    LDSM_X4(alr[i][0], alr[i][1], alr[i][2], alr[i][3], aLoB + ko + i * 1280);
#pragma unroll
                for (int i = 0; i < 2; ++i)
#pragma unroll
                    for (int j = 0; j < 4; ++j) mma_bf16(c[i][j], alr[i], bb[j]);

#pragma unroll
                for (int j2 = 0; j2 < 2; ++j2)
                    LDSM_X4(bb[2 * j2][0], bb[2 * j2][1], bb[2 * j2 + 1][0], bb[2 * j2 + 1][1],
                            bLoB + ko + j2 * 1280);
#pragma unroll
                for (int i = 0; i < 2; ++i)
#pragma unroll
                    for (int j = 0; j < 4; ++j) mma_bf16(c[i][j], ahr[i], bb[j]);
            }
        }
    }
    __syncthreads();

    float (*Hs)[65] = (float (*)[65])dsm;
    const int colBase = wn * 32 + (lane & 3) * 2;
    const int rowB    = wm * 32 + (lane >> 2);
#pragma unroll
    for (int j = 0; j < 4; ++j) {
        const int col = colBase + j * 8;
        const float b0 = bbv[col], b1 = bbv[col + 1];
#pragma unroll
        for (int i = 0; i < 2; ++i) {
            const int r = rowB + i * 16;
            Hs[r][col]         = c[i][j][0] + b0;
            Hs[r][col + 1]     = c[i][j][1] + b1;
            Hs[r + 8][col]     = c[i][j][2] + b0;
            Hs[r + 8][col + 1] = c[i][j][3] + b1;
        }
    }
    __syncthreads();

    const float g0  = gamma[lane], g1  = gamma[lane + 32];
    const float be0 = beta[lane],  be1 = beta[lane + 32];
#pragma unroll
    for (int rr = 0; rr < 16; ++rr) {
        const int r = wid * 16 + rr;
        float x0 = Hs[r][lane], x1 = Hs[r][lane + 32];
        float s  = x0 + x1;
        float s2 = x0 * x0 + x1 * x1;
#pragma unroll
        for (int o = 16; o > 0; o >>= 1) {
            s  += __shfl_xor_sync(0xffffffffu, s, o);
            s2 += __shfl_xor_sync(0xffffffffu, s2, o);
        }
        float mu  = s * (1.0f / 64.0f);
        float var = s2 * (1.0f / 64.0f) - mu * mu;
        float inv = rsqrtf(var + 1e-5f);
        float y0 = (x0 - mu) * inv * g0 + be0;
        float y1 = (x1 - mu) * inv * g1 + be1;
        out[(size_t)(row0 + r) * 64 + lane]      = fmaxf(y0, 0.0f);
        out[(size_t)(row0 + r) * 64 + lane + 32] = fmaxf(y1, 0.0f);
    }
}

// ============================================================
extern "C" void kernel_launch(void* const* d_in, const int* in_sizes, int n_in,
                              void* d_out, int out_size)
{
    (void)in_sizes; (void)n_in; (void)out_size;
    const float* L0 = (const float*)d_in[0];
    const float* W0 = (const float*)d_in[1];
    const float* b0 = (const float*)d_in[2];
    const float* L1 = (const float*)d_in[3];
    const float* W1 = (const float*)d_in[4];
    const float* b1 = (const float*)d_in[5];
    const float* L2 = (const float*)d_in[6];
    const float* W2 = (const float*)d_in[7];
    const float* b2 = (const float*)d_in[8];
    const float* corr  = (const float*)d_in[9];
    const float* Wb    = (const float*)d_in[10];
    const float* bb    = (const float*)d_in[11];
    const float* gamma = (const float*)d_in[12];
    const float* beta  = (const float*)d_in[13];
    float* out = (float*)d_out;

    cudaFuncSetAttribute(proj_mma_kernel, cudaFuncAttributeMaxDynamicSharedMemorySize, SMEM_PROJ);
    cudaFuncSetAttribute(ccsm_mma_kernel, cudaFuncAttributeMaxDynamicSharedMemorySize, SMEM_CS);
    cudaFuncSetAttribute(attfuse_mma_kernel, cudaFuncAttributeMaxDynamicSharedMemorySize, SMEM_AT);
    cudaFuncSetAttribute(final_mma_kernel, cudaFuncAttributeMaxDynamicSharedMemorySize, SMEM_FIN);

    wconv_kernel<<<dim3(192, 3), 256>>>(W0, W1, W2);
    wbconv_kernel<<<64, 256>>>(Wb);
    cprep_kernel<<<64, 256>>>(corr);
    proj_mma_kernel<<<dim3(256, 3), 256, SMEM_PROJ>>>(L0, L1, L2, b0, b1, b2);
    ccsm_mma_kernel<<<dim3(512, 2), 256, SMEM_CS>>>();
    attfuse_mma_kernel<<<dim3(512, 4), 256, SMEM_AT>>>();
    final_mma_kernel<<<256, 256, SMEM_FIN>>>(bb, gamma, beta, out);
}

// round 16
// speedup vs baseline: 1.0506x; 1.0506x over previous
#include <cuda_runtime.h>
#include <cuda_bf16.h>
#include <cstdint>

// Problem constants
namespace {
constexpr int Bn  = 512;
constexpr int Sn  = 64;
constexpr int En  = 768;
constexpr int Dn  = 256;
constexpr int BS  = Bn * Sn;     // 32768
constexpr int FIN = 1024;        // 2*D*(M-1)
}

// ---- scratch (device globals: allocation-free rule) ----
__device__ float g_proj[3][(size_t)BS * Dn];      // projected modalities [3][B*S, D]
__device__ float g_t[(size_t)BS * Dn];            // anchor @ corr        [B*S, D]
__device__ float g_aT[2][(size_t)Bn * Sn * Sn];   // a_att transposed: [b][j][i]
__device__ float g_o[2][(size_t)Bn * Sn * Sn];    // o_att:            [b][i][j]
__device__ __align__(256) __nv_bfloat16 g_Wh[3 * Dn * En];  // weight hi parts
__device__ __align__(256) __nv_bfloat16 g_Wl[3 * Dn * En];  // weight lo parts
__device__ __align__(256) __nv_bfloat16 g_Ch[Dn * Dn];      // corr^T hi [n][k]
__device__ __align__(256) __nv_bfloat16 g_Cl[Dn * Dn];      // corr^T lo
__device__ __align__(256) __nv_bfloat16 g_fh[(size_t)BS * FIN];  // fused hi
__device__ __align__(256) __nv_bfloat16 g_fl[(size_t)BS * FIN];  // fused lo
__device__ __align__(256) __nv_bfloat16 g_Wbh[64 * FIN];         // Wb hi
__device__ __align__(256) __nv_bfloat16 g_Wbl[64 * FIN];         // Wb lo

// ============================================================
// helpers (baseline PTX only)
// ============================================================
__device__ __forceinline__ uint32_t smem_u32(const void* p) {
    uint32_t a;
    asm("{ .reg .u64 t; cvta.to.shared.u64 t, %1; cvt.u32.u64 %0, t; }" : "=r"(a) : "l"(p));
    return a;
}
#define CP_ASYNC16(dst, src) \
    asm volatile("cp.async.cg.shared.global [%0], [%1], 16;" :: "r"(dst), "l"(src))
#define CP_COMMIT() asm volatile("cp.async.commit_group;" ::: "memory")
#define CP_WAIT0()  asm volatile("cp.async.wait_group 0;" ::: "memory")
#define CP_WAIT1()  asm volatile("cp.async.wait_group 1;" ::: "memory")

#define LDSM_X4(r0, r1, r2, r3, addr) \
    asm volatile("ldmatrix.sync.aligned.m8n8.x4.shared.b16 {%0,%1,%2,%3}, [%4];" \
                 : "=r"(r0), "=r"(r1), "=r"(r2), "=r"(r3) : "r"(addr))

#define LDSM_X4_T(r0, r1, r2, r3, addr) \
    asm volatile("ldmatrix.sync.aligned.m8n8.x4.trans.shared.b16 {%0,%1,%2,%3}, [%4];" \
                 : "=r"(r0), "=r"(r1), "=r"(r2), "=r"(r3) : "r"(addr))

__device__ __forceinline__ void mma_bf16(float* c, const uint32_t* a, const uint32_t* b) {
    asm volatile(
        "mma.sync.aligned.m16n8k16.row.col.f32.bf16.bf16.f32 "
        "{%0,%1,%2,%3}, {%4,%5,%6,%7}, {%8,%9}, {%0,%1,%2,%3};"
        : "+f"(c[0]), "+f"(c[1]), "+f"(c[2]), "+f"(c[3])
        : "r"(a[0]), "r"(a[1]), "r"(a[2]), "r"(a[3]), "r"(b[0]), "r"(b[1]));
}

__device__ __forceinline__ uint32_t pk_bf16x2(float lo, float hi) {
    uint32_t r;
    asm("cvt.rn.bf16x2.f32 %0, %1, %2;" : "=r"(r) : "f"(hi), "f"(lo));
    return r;
}
__device__ __forceinline__ float bf16bits_f(uint32_t b16) { return __uint_as_float(b16 << 16); }

__device__ __forceinline__ void split4(float4 v, uint2& hi, uint2& lo) {
    uint32_t h01 = pk_bf16x2(v.x, v.y);
    uint32_t h23 = pk_bf16x2(v.z, v.w);
    float rx = v.x - bf16bits_f(h01 & 0xffffu);
    float ry = v.y - bf16bits_f(h01 >> 16);
    float rz = v.z - bf16bits_f(h23 & 0xffffu);
    float rw = v.w - bf16bits_f(h23 >> 16);
    hi.x = h01; hi.y = h23;
    lo.x = pk_bf16x2(rx, ry);
    lo.y = pk_bf16x2(rz, rw);
}

__device__ __forceinline__ void split1(float v, __nv_bfloat16* hp, __nv_bfloat16* lp) {
    __nv_bfloat16 h = __float2bfloat16(v);
    *hp = h;
    *lp = __float2bfloat16(v - __bfloat162float(h));
}

// ============================================================
// Kernel B: convert weights fp32 -> bf16 hi/lo (3 modalities)
// ============================================================
__global__ __launch_bounds__(256) void wconv_kernel(
    const float* __restrict__ W0, const float* __restrict__ W1, const float* __restrict__ W2)
{
    const int m = blockIdx.y;
    const float* W = (m == 0) ? W0 : (m == 1) ? W1 : W2;
    const size_t base = (size_t)m * Dn * En;
    int idx = (blockIdx.x * 256 + threadIdx.x) * 4;
    float4 v = *(const float4*)(W + idx);
    uint2 hi, lo;
    split4(v, hi, lo);
    *(uint2*)(g_Wh + base + idx) = hi;
    *(uint2*)(g_Wl + base + idx) = lo;
}

__global__ __launch_bounds__(256) void wbconv_kernel(const float* __restrict__ Wb)
{
    int idx = (blockIdx.x * 256 + threadIdx.x) * 4;
    float4 v = *(const float4*)(Wb + idx);
    uint2 hi, lo;
    split4(v, hi, lo);
    *(uint2*)(g_Wbh + idx) = hi;
    *(uint2*)(g_Wbl + idx) = lo;
}

// corr^T split: g_Ch/g_Cl[n][k] = split(corr[k][n]); 256x256
__global__ __launch_bounds__(256) void cprep_kernel(const float* __restrict__ corr)
{
    __shared__ float tile[32][33];
    const int n0 = (blockIdx.x & 7) * 32;
    const int k0 = (blockIdx.x >> 3) * 32;
    const int tr = threadIdx.x >> 5, tc = threadIdx.x & 31;
    for (int r = tr; r < 32; r += 8)
        tile[r][tc] = corr[(size_t)(k0 + r) * Dn + n0 + tc];
    __syncthreads();
    for (int r = tr; r < 32; r += 8) {
        float v = tile[tc][r];
        split1(v, &g_Ch[(size_t)(n0 + r) * Dn + k0 + tc], &g_Cl[(size_t)(n0 + r) * Dn + k0 + tc]);
    }
}

// ============================================================
// Kernel C: HMMA projection GEMM, 256 threads / 8 warps (2M x 4N),
// warp tile 64x64, 3-stage cp.async pipeline. K=768, z in {0,1,2}.
// z==0 additionally computes g_t = tile @ corrT^T (fused tmat).
// ============================================================
namespace {
constexpr int NCHUNK = En / 32;                 // 24
constexpr uint32_t SZ_A  = 128 * 80;            // 10240
constexpr uint32_t SZ_B  = 256 * 80;            // 20480
constexpr uint32_t STAGE = 2 * SZ_A + 2 * SZ_B; // 61440
constexpr uint32_t TD_HI = 0;                   // 8 chunks x 10240
constexpr uint32_t TD_LO = 81920;
constexpr uint32_t TD_B  = 163840;              // 2 stages x 20480
constexpr uint32_t SMEM_PROJ = 204800;
}

__global__ __launch_bounds__(256, 1)
void proj_mma_kernel(const float* __restrict__ L0, const float* __restrict__ L1,
                     const float* __restrict__ L2,
                     const float* __restrict__ P0, const float* __restrict__ P1,
                     const float* __restrict__ P2)
{
    extern __shared__ char dsm[];
    const uint32_t sb = smem_u32(dsm);
    const int tid  = threadIdx.x;
    const int lane = tid & 31;
    const int wid  = tid >> 5;
    const int wm   = wid & 1;
    const int wn   = wid >> 1;
    const int z    = blockIdx.y;
    const int row0 = blockIdx.x * 128;

    const float* A = (z == 1) ? L1 : (z == 2) ? L2 : L0;
    const __nv_bfloat16* Wh = g_Wh + (size_t)z * Dn * En;
    const __nv_bfloat16* Wl = g_Wl + (size_t)z * Dn * En;

    const int bn   = tid >> 2;
    const int bseg = tid & 3;
    const int ar = tid >> 1;
    const int ah = tid & 1;

    float4 af[4];

    const uint32_t aOff = (uint32_t)((wm * 64 + (lane & 15)) * 80 + (lane >> 4) * 16);
    const uint32_t bOff = (uint32_t)((wn * 64 + (lane & 7) + ((lane >> 4) << 3)) * 80 +
                                     ((lane >> 3) & 1) * 16);

    float c[4][8][4] = {};

    {
#pragma unroll
        for (int pc = 0; pc < 2; ++pc) {
            const uint32_t bhi = sb + pc * STAGE + 2 * SZ_A;
            const uint32_t blo = bhi + SZ_B;
            const int k0 = pc * 32;
#pragma unroll
            for (int r = 0; r < 4; ++r) {
                int row = bn + r * 64;
                CP_ASYNC16(bhi + row * 80 + bseg * 16, Wh + (size_t)row * 768 + k0 + bseg * 8);
                CP_ASYNC16(blo + row * 80 + bseg * 16, Wl + (size_t)row * 768 + k0 + bseg * 8);
            }
            CP_COMMIT();
        }
        const float* p = A + (size_t)(row0 + ar) * 768 + ah * 16;
        af[0] = *(const float4*)(p);
        af[1] = *(const float4*)(p + 4);
        af[2] = *(const float4*)(p + 8);
        af[3] = *(const float4*)(p + 12);
    }

    int st = 0;
#pragma unroll 1
    for (int ch = 0; ch < NCHUNK; ++ch) {
        {
            char* ahi = dsm + st * STAGE;
            char* alo = ahi + SZ_A;
            const uint32_t off = (uint32_t)(ar * 80 + ah * 32);
#pragma unroll
            for (int q = 0; q < 4; ++q) {
                uint2 hi, lo;
                split4(af[q], hi, lo);
                *(uint2*)(ahi + off + q * 8) = hi;
                *(uint2*)(alo + off + q * 8) = lo;
            }
        }
        if (ch < NCHUNK - 1) {
            const float* p = A + (size_t)(row0 + ar) * 768 + (ch + 1) * 32 + ah * 16;
            af[0] = *(const float4*)(p);
            af[1] = *(const float4*)(p + 4);
            af[2] = *(const float4*)(p + 8);
            af[3] = *(const float4*)(p + 12);
        }
        if (ch < NCHUNK - 1) { CP_WAIT1(); } else { CP_WAIT0(); }
        __syncthreads();
        if (ch + 2 < NCHUNK) {
            const int st2 = (st >= 1) ? st - 1 : st + 2;
            const int k2 = (ch + 2) * 32;
            const uint32_t bhi = sb + st2 * STAGE + 2 * SZ_A;
            const uint32_t blo = bhi + SZ_B;
#pragma unroll
            for (int r = 0; r < 4; ++r) {
                int row = bn + r * 64;
                CP_ASYNC16(bhi + row * 80 + bseg * 16, Wh + (size_t)row * 768 + k2 + bseg * 8);
                CP_ASYNC16(blo + row * 80 + bseg * 16, Wl + (size_t)row * 768 + k2 + bseg * 8);
            }
            CP_COMMIT();
        }
        {
            const uint32_t aHiB = sb + st * STAGE + aOff;
            const uint32_t aLoB = aHiB + SZ_A;
            const uint32_t bHiB = sb + st * STAGE + 2 * SZ_A + bOff;
            const uint32_t bLoB = bHiB + SZ_B;
#pragma unroll
            for (int ks = 0; ks < 2; ++ks) {
                const uint32_t ko = ks * 32;
                uint32_t ahr[4][4], bb[8][2];
#pragma unroll
                for (int i = 0; i < 4; ++i)
                    LDSM_X4(ahr[i][0], ahr[i][1], ahr[i][2], ahr[i][3], aHiB + ko + i * 1280);
#pragma unroll
                for (int j2 = 0; j2 < 4; ++j2)
                    LDSM_X4(bb[2 * j2][0], bb[2 * j2][1], bb[2 * j2 + 1][0], bb[2 * j2 + 1][1],
                            bHiB + ko + j2 * 1280);
#pragma unroll
                for (int i = 0; i < 4; ++i)
#pragma unroll
                    for (int j = 0; j < 8; ++j) mma_bf16(c[i][j], ahr[i], bb[j]);

                uint32_t alr[4][4];
#pragma unroll
                for (int i = 0; i < 4; ++i)
                    LDSM_X4(alr[i][0], alr[i][1], alr[i][2], alr[i][3], aLoB + ko + i * 1280);
#pragma unroll
                for (int i = 0; i < 4; ++i)
#pragma unroll
                    for (int j = 0; j < 8; ++j) mma_bf16(c[i][j], alr[i], bb[j]);

#pragma unroll
                for (int j2 = 0; j2 < 4; ++j2)
                    LDSM_X4(bb[2 * j2][0], bb[2 * j2][1], bb[2 * j2 + 1][0], bb[2 * j2 + 1][1],
                            bLoB + ko + j2 * 1280);
#pragma unroll
                for (int i = 0; i < 4; ++i)
#pragma unroll
                    for (int j = 0; j < 8; ++j) mma_bf16(c[i][j], ahr[i], bb[j]);
            }
        }
        st = (st == 2) ? 0 : st + 1;
    }

    const float* bias = (z == 0) ? P0 : (z == 1) ? P1 : P2;
    float* Cout = g_proj[z];
    const int colBase = wn * 64 + (lane & 3) * 2;
    const int rowBase = row0 + wm * 64 + (lane >> 2);
#pragma unroll
    for (int j = 0; j < 8; ++j) {
        const int col = colBase + j * 8;
        const float b0 = bias[col], b1 = bias[col + 1];
#pragma unroll
        for (int i = 0; i < 4; ++i) {
            const int r = rowBase + i * 16;
            float2 lo2 = make_float2(c[i][j][0] + b0, c[i][j][1] + b1);
            float2 hi2 = make_float2(c[i][j][2] + b0, c[i][j][3] + b1);
            *(float2*)(Cout + (size_t)r * 256 + col)       = lo2;
            *(float2*)(Cout + (size_t)(r + 8) * 256 + col) = hi2;
        }
    }

    if (z != 0) return;

    // ================= fused tmat (z==0 only) =================
    __syncthreads();
    {
        const int lr = wm * 64 + (lane >> 2);
#pragma unroll
        for (int j = 0; j < 8; ++j) {
            const int col = colBase + j * 8;
            const float b0 = bias[col], b1 = bias[col + 1];
            const int kc = col >> 5, c32 = col & 31;
#pragma unroll
            for (int i = 0; i < 4; ++i) {
#pragma unroll
                for (int half = 0; half < 2; ++half) {
                    const int r = lr + i * 16 + half * 8;
                    float v0 = c[i][j][half * 2 + 0] + b0;
                    float v1 = c[i][j][half * 2 + 1] + b1;
                    uint32_t hh = pk_bf16x2(v0, v1);
                    float q0 = v0 - bf16bits_f(hh & 0xffffu);
                    float q1 = v1 - bf16bits_f(hh >> 16);
                    uint32_t ll = pk_bf16x2(q0, q1);
                    *(uint32_t*)(dsm + TD_HI + kc * 10240 + r * 80 + c32 * 2) = hh;
                    *(uint32_t*)(dsm + TD_LO + kc * 10240 + r * 80 + c32 * 2) = ll;
                }
            }
        }
    }
    const int tbrow = tid >> 1;
    const int tbs   = (tid & 1) * 2;
    {
        const uint32_t bhi = sb + TD_B;
        const uint32_t blo = bhi + 10240;
#pragma unroll
        for (int s = 0; s < 2; ++s) {
            int seg = tbs + s;
            CP_ASYNC16(bhi + tbrow * 80 + seg * 16, g_Ch + (size_t)tbrow * 256 + seg * 8);
            CP_ASYNC16(blo + tbrow * 80 + seg * 16, g_Cl + (size_t)tbrow * 256 + seg * 8);
        }
        CP_COMMIT();
    }

    const uint32_t a2off = (uint32_t)((wm * 64 + (lane & 15)) * 80 + (lane >> 4) * 16);
    const uint32_t b2off = (uint32_t)((wn * 32 + (lane & 7) + ((lane >> 4) << 3)) * 80 +
                                      ((lane >> 3) & 1) * 16);
    float c2[4][4][4] = {};

#pragma unroll 1
    for (int it = 0; it < 16; ++it) {
        const int stg = it & 1;
        const int nh = it >> 3, kc = it & 7;
        CP_WAIT0();
        __syncthreads();
        if (it < 15) {
            const int nh1 = (it + 1) >> 3, kc1 = (it + 1) & 7;
            const uint32_t bhi = sb + TD_B + (stg ^ 1) * 20480;
            const uint32_t blo = bhi + 10240;
#pragma unroll
            for (int s = 0; s < 2; ++s) {
                int seg = tbs + s;
                CP_ASYNC16(bhi + tbrow * 80 + seg * 16,
                           g_Ch + (size_t)(nh1 * 128 + tbrow) * 256 + kc1 * 32 + seg * 8);
                CP_ASYNC16(blo + tbrow * 80 + seg * 16,
                           g_Cl + (size_t)(nh1 * 128 + tbrow) * 256 + kc1 * 32 + seg * 8);
            }
            CP_COMMIT();
        }
        {
            const uint32_t aHiB = sb + TD_HI + kc * 10240 + a2off;
            const uint32_t aLoB = aHiB + (TD_LO - TD_HI);
            const uint32_t bHiB = sb + TD_B + stg * 20480 + b2off;
            const uint32_t bLoB = bHiB + 10240;
#pragma unroll
            for (int ks = 0; ks < 2; ++ks) {
                const uint32_t ko = ks * 32;
                uint32_t ahr[4][4], bb[4][2];
#pragma unroll
                for (int i = 0; i < 4; ++i)
                    LDSM_X4(ahr[i][0], ahr[i][1], ahr[i][2], ahr[i][3], aHiB + ko + i * 1280);
#pragma unroll
                for (int j2 = 0; j2 < 2; ++j2)
                    LDSM_X4(bb[2 * j2][0], bb[2 * j2][1], bb[2 * j2 + 1][0], bb[2 * j2 + 1][1],
                            bHiB + ko + j2 * 1280);
#pragma unroll
                for (int i = 0; i < 4; ++i)
#pragma unroll
                    for (int j = 0; j < 4; ++j) mma_bf16(c2[i][j], ahr[i], bb[j]);

                uint32_t alr[4][4];
#pragma unroll
                for (int i = 0; i < 4; ++i)
                    LDSM_X4(alr[i][0], alr[i][1], alr[i][2], alr[i][3], aLoB + ko + i * 1280);
#pragma unroll
                for (int i = 0; i < 4; ++i)
#pragma unroll
                    for (int j = 0; j < 4; ++j) mma_bf16(c2[i][j], alr[i], bb[j]);

#pragma unroll
                for (int j2 = 0; j2 < 2; ++j2)
                    LDSM_X4(bb[2 * j2][0], bb[2 * j2][1], bb[2 * j2 + 1][0], bb[2 * j2 + 1][1],
                            bLoB + ko + j2 * 1280);
#pragma unroll
                for (int i = 0; i < 4; ++i)
#pragma unroll
                    for (int j = 0; j < 4; ++j) mma_bf16(c2[i][j], ahr[i], bb[j]);
            }
        }
        if (kc == 7) {
            const int colB2 = nh * 128 + wn * 32 + (lane & 3) * 2;
#pragma unroll
            for (int j = 0; j < 4; ++j) {
                const int col = colB2 + j * 8;
#pragma unroll
                for (int i = 0; i < 4; ++i) {
                    const int r = rowBase + i * 16;
                    float2 lo2 = make_float2(c2[i][j][0], c2[i][j][1]);
                    float2 hi2 = make_float2(c2[i][j][2], c2[i][j][3]);
                    *(float2*)(g_t + (size_t)r * 256 + col)       = lo2;
                    *(float2*)(g_t + (size_t)(r + 8) * 256 + col) = hi2;
                }
            }
#pragma unroll
            for (int i = 0; i < 4; ++i)
#pragma unroll
                for (int j = 0; j < 4; ++j)
#pragma unroll
                    for (int q = 0; q < 4; ++q) c2[i][j][q] = 0.f;
        }
    }
}

// ============================================================
// Kernel 3 (HMMA): per (b,p): cc = T @ O^T via mma.sync (bf16 split),
// dual softmax in smem.
// ============================================================
namespace {
constexpr uint32_t CS_TH = 0;                      // 64 x 144B
constexpr uint32_t CS_TL = 64 * 144;               // 9216
constexpr uint32_t CS_OH = 2 * 64 * 144;           // 18432
constexpr uint32_t CS_OL = 3 * 64 * 144;           // 27648
constexpr uint32_t CS_SC = 4 * 64 * 144;           // 36864 (floats [64][65])
constexpr uint32_t SMEM_CS = CS_SC + 64 * 65 * 4;  // 53504
}

__global__ __launch_bounds__(256) void ccsm_mma_kernel()
{
    extern __shared__ char dsm[];
    const uint32_t sb = smem_u32(dsm);
    const int b = blockIdx.x;
    const int p = blockIdx.y;
    const float* T = g_t + (size_t)b * Sn * Dn;
    const float* O = g_proj[p + 1] + (size_t)b * Sn * Dn;

    const int tid = threadIdx.x;
    const int lane = tid & 31;
    const int wid  = tid >> 5;
    const int wm   = wid & 1;
    const int wn   = wid >> 1;

    const uint32_t aBase = sb + CS_TH +
        (uint32_t)((wm * 32 + (lane & 15)) * 144 + (lane >> 4) * 16);
    const uint32_t bBase = sb + CS_OH +
        (uint32_t)((wn * 16 + (lane & 7) + ((lane >> 4) << 3)) * 144 + ((lane >> 3) & 1) * 16);

    float c[2][2][4] = {};

#pragma unroll 1
    for (int kc = 0; kc < 4; ++kc) {
        {
            char* th = dsm + CS_TH; char* tl = dsm + CS_TL;
            char* oh = dsm + CS_OH; char* ol = dsm + CS_OL;
#pragma unroll
            for (int q = 0; q < 4; ++q) {
                int idx = (q * 256 + tid) * 4;
                int r = idx >> 6, c0 = idx & 63;
                float4 vT = *(const float4*)(T + (size_t)r * 256 + kc * 64 + c0);
                float4 vO = *(const float4*)(O + (size_t)r * 256 + kc * 64 + c0);
                uint2 h, l;
                split4(vT, h, l);
                *(uint2*)(th + r * 144 + c0 * 2) = h;
                *(uint2*)(tl + r * 144 + c0 * 2) = l;
                split4(vO, h, l);
                *(uint2*)(oh + r * 144 + c0 * 2) = h;
                *(uint2*)(ol + r * 144 + c0 * 2) = l;
            }
        }
        __syncthreads();
#pragma unroll
        for (int ks = 0; ks < 4; ++ks) {
            const uint32_t ko = (uint32_t)(ks * 32);
            uint32_t ahr[2][4], bb[2][2];
#pragma unroll
            for (int i = 0; i < 2; ++i)
                LDSM_X4(ahr[i][0], ahr[i][1], ahr[i][2], ahr[i][3], aBase + ko + i * 16 * 144);
            LDSM_X4(bb[0][0], bb[0][1], bb[1][0], bb[1][1], bBase + ko);
#pragma unroll
            for (int i = 0; i < 2; ++i)
#pragma unroll
                for (int j = 0; j < 2; ++j) mma_bf16(c[i][j], ahr[i], bb[j]);

            uint32_t alr[2][4];
#pragma unroll
            for (int i = 0; i < 2; ++i)
                LDSM_X4(alr[i][0], alr[i][1], alr[i][2], alr[i][3],
                        aBase + (CS_TL - CS_TH) + ko + i * 16 * 144);
#pragma unroll
            for (int i = 0; i < 2; ++i)
#pragma unroll
                for (int j = 0; j < 2; ++j) mma_bf16(c[i][j], alr[i], bb[j]);

            uint32_t bl[2][2];
            LDSM_X4(bl[0][0], bl[0][1], bl[1][0], bl[1][1], bBase + (CS_OL - CS_OH) + ko);
#pragma unroll
            for (int i = 0; i < 2; ++i)
#pragma unroll
                for (int j = 0; j < 2; ++j) mma_bf16(c[i][j], ahr[i], bl[j]);
        }
        __syncthreads();
    }

    float* sc = (float*)(dsm + CS_SC);
    {
        const int rowB = wm * 32 + (lane >> 2);
        const int colB = wn * 16 + (lane & 3) * 2;
#pragma unroll
        for (int i = 0; i < 2; ++i)
#pragma unroll
            for (int j = 0; j < 2; ++j) {
                sc[(rowB + i * 16)     * 65 + colB + j * 8]     = c[i][j][0];
                sc[(rowB + i * 16)     * 65 + colB + j * 8 + 1] = c[i][j][1];
                sc[(rowB + i * 16 + 8) * 65 + colB + j * 8]     = c[i][j][2];
                sc[(rowB + i * 16 + 8) * 65 + colB + j * 8 + 1] = c[i][j][3];
            }
    }
    __syncthreads();

    const int warp = wid, lane2 = lane;
    float* orow  = g_o[p]  + (size_t)b * Sn * Sn;
    float* aTrow = g_aT[p] + (size_t)b * Sn * Sn;

    for (int r = warp; r < 64; r += 8) {
        float x0 = sc[r * 65 + lane2], x1 = sc[r * 65 + lane2 + 32];
        float mx = fmaxf(x0, x1);
#pragma unroll
        for (int o = 16; o > 0; o >>= 1) mx = fmaxf(mx, __shfl_xor_sync(0xffffffffu, mx, o));
        float e0 = __expf(x0 - mx), e1 = __expf(x1 - mx);
        float s = e0 + e1;
#pragma unroll
        for (int o = 16; o > 0; o >>= 1) s += __shfl_xor_sync(0xffffffffu, s, o);
        float inv = 1.0f / s;
        orow[r * 64 + lane2]      = e0 * inv;
        orow[r * 64 + lane2 + 32] = e1 * inv;
    }
    for (int cix = warp; cix < 64; cix += 8) {
        float x0 = sc[lane2 * 65 + cix], x1 = sc[(lane2 + 32) * 65 + cix];
        float mx = fmaxf(x0, x1);
#pragma unroll
        for (int o = 16; o > 0; o >>= 1) mx = fmaxf(mx, __shfl_xor_sync(0xffffffffu, mx, o));
        float e0 = __expf(x0 - mx), e1 = __expf(x1 - mx);
        float s = e0 + e1;
#pragma unroll
        for (int o = 16; o > 0; o >>= 1) s += __shfl_xor_sync(0xffffffffu, s, o);
        float inv = 1.0f / s;
        aTrow[cix * 64 + lane2]      = e0 * inv;
        aTrow[cix * 64 + lane2 + 32] = e1 * inv;
    }
}

// ============================================================
// Kernel 4 (HMMA): att GEMM + residual -> fused bf16 hi/lo.
// ============================================================
namespace {
constexpr uint32_t AT_A_H = 0;                       // 64 rows x 144B
constexpr uint32_t AT_A_L = 64 * 144;                // 9216
constexpr uint32_t AT_X_H = 2 * 64 * 144;            // 18432; 64 rows x 528B
constexpr uint32_t AT_X_L = AT_X_H + 64 * 528;       // 52224
constexpr uint32_t SMEM_AT = AT_X_L + 64 * 528;      // 86016
}

__global__ __launch_bounds__(256)
void attfuse_mma_kernel()
{
    extern __shared__ char dsm[];
    const uint32_t sb = smem_u32(dsm);
    const int b    = blockIdx.x;
    const int p    = blockIdx.y >> 1;
    const int side = blockIdx.y & 1;
    const int tid  = threadIdx.x;
    const int lane = tid & 31;
    const int wid  = tid >> 5;
    const int wm   = wid & 1;
    const int wn   = wid >> 1;

    const float* Mat = (side == 0) ? (g_aT[p] + (size_t)b * 4096)
                                   : (g_o[p]  + (size_t)b * 4096);
    const float* X   = (side == 0) ? (g_proj[0]     + (size_t)b * Sn * Dn)
                                   : (g_proj[p + 1] + (size_t)b * Sn * Dn);

    {
        char* ahp = dsm + AT_A_H;
        char* alp = dsm + AT_A_L;
#pragma unroll
        for (int q = 0; q < 4; ++q) {
            int idx = (q * 256 + tid) * 4;
            float4 v = *(const float4*)(Mat + idx);
            int r = idx >> 6, c0 = idx & 63;
            uint2 hi, lo;
            split4(v, hi, lo);
            *(uint2*)(ahp + r * 144 + c0 * 2) = hi;
            *(uint2*)(alp + r * 144 + c0 * 2) = lo;
        }
    }
    {
        char* xhp = dsm + AT_X_H;
        char* xlp = dsm + AT_X_L;
#pragma unroll
        for (int q = 0; q < 16; ++q) {
            int idx = (q * 256 + tid) * 4;
            float4 v = *(const float4*)(X + idx);
            int r = idx >> 8, c0 = idx & 255;
            uint2 hi, lo;
            split4(v, hi, lo);
            *(uint2*)(xhp + r * 528 + c0 * 2) = hi;
            *(uint2*)(xlp + r * 528 + c0 * 2) = lo;
        }
    }
    __syncthreads();

    const uint32_t aHiB = sb + AT_A_H + (uint32_t)((wm * 32 + (lane & 15)) * 144 + (lane >> 4) * 16);
    const uint32_t aLoB = aHiB + (AT_A_L - AT_A_H);
    const uint32_t bHiB = sb + AT_X_H + (uint32_t)((lane & 15) * 528 + (wn * 64 + (lane >> 4) * 8) * 2);
    const uint32_t bLoB = bHiB + (AT_X_L - AT_X_H);

    float c[2][8][4] = {};

#pragma unroll 1
    for (int ks = 0; ks < 4; ++ks) {
        const uint32_t ak = (uint32_t)(ks * 32);
        const uint32_t bk = (uint32_t)(ks * 16 * 528);
        uint32_t ahr[2][4], bb[8][2];
#pragma unroll
        for (int i = 0; i < 2; ++i)
            LDSM_X4(ahr[i][0], ahr[i][1], ahr[i][2], ahr[i][3], aHiB + ak + i * 16 * 144);
#pragma unroll
        for (int j2 = 0; j2 < 4; ++j2)
            LDSM_X4_T(bb[2 * j2][0], bb[2 * j2][1], bb[2 * j2 + 1][0], bb[2 * j2 + 1][1],
                      bHiB + bk + j2 * 32);
#pragma unroll
        for (int i = 0; i < 2; ++i)
#pragma unroll
            for (int j = 0; j < 8; ++j) mma_bf16(c[i][j], ahr[i], bb[j]);

        uint32_t alr[2][4];
#pragma unroll
        for (int i = 0; i < 2; ++i)
            LDSM_X4(alr[i][0], alr[i][1], alr[i][2], alr[i][3], aLoB + ak + i * 16 * 144);
#pragma unroll
        for (int i = 0; i < 2; ++i)
#pragma unroll
            for (int j = 0; j < 8; ++j) mma_bf16(c[i][j], alr[i], bb[j]);

#pragma unroll
        for (int j2 = 0; j2 < 4; ++j2)
            LDSM_X4_T(bb[2 * j2][0], bb[2 * j2][1], bb[2 * j2 + 1][0], bb[2 * j2 + 1][1],
                      bLoB + bk + j2 * 32);
#pragma unroll
        for (int i = 0; i < 2; ++i)
#pragma unroll
            for (int j = 0; j < 8; ++j) mma_bf16(c[i][j], ahr[i], bb[j]);
    }

    const char* xhp = dsm + AT_X_H;
    const char* xlp = dsm + AT_X_L;
    const int rowBase = wm * 32 + (lane >> 2);
    const int colBase = wn * 64 + (lane & 3) * 2;
    const size_t dstBase = (size_t)(b * 64) * FIN + p * 512 + side * 256;
#pragma unroll
    for (int i = 0; i < 2; ++i) {
#pragma unroll
        for (int j = 0; j < 8; ++j) {
            const int col = colBase + j * 8;
#pragma unroll
            for (int half = 0; half < 2; ++half) {
                const int r = rowBase + i * 16 + half * 8;
                uint32_t rh = *(const uint32_t*)(xhp + r * 528 + col * 2);
                uint32_t rl = *(const uint32_t*)(xlp + r * 528 + col * 2);
                float res0 = bf16bits_f(rh & 0xffffu) + bf16bits_f(rl & 0xffffu);
                float res1 = bf16bits_f(rh >> 16)     + bf16bits_f(rl >> 16);
                float v0 = c[i][j][half * 2 + 0] + res0;
                float v1 = c[i][j][half * 2 + 1] + res1;
                uint32_t hh = pk_bf16x2(v0, v1);
                float q0 = v0 - bf16bits_f(hh & 0xffffu);
                float q1 = v1 - bf16bits_f(hh >> 16);
                uint32_t ll = pk_bf16x2(q0, q1);
                size_t e = dstBase + (size_t)r * FIN + col;
                *(uint32_t*)(g_fh + e) = hh;
                *(uint32_t*)(g_fl + e) = ll;
            }
        }
    }
}

// ============================================================
// Kernel 5: HMMA final: h = fused @ Wb^T + bb; LayerNorm(64); ReLU
// 3-stage cp.async pipeline (wait_group 1), 2 CTAs/SM.
// ============================================================
namespace {
constexpr int FNCH = FIN / 32;                    // 32
constexpr uint32_t F_SZ_A = 128 * 80;             // 10240
constexpr uint32_t F_SZ_B = 64 * 80;              // 5120
constexpr uint32_t F_STAGE = 2 * F_SZ_A + 2 * F_SZ_B;  // 30720
constexpr uint32_t SMEM_FIN = 3 * F_STAGE;        // 92160
}

__global__ __launch_bounds__(256, 2)
void final_mma_kernel(const float* __restrict__ bbv,
                      const float* __restrict__ gamma, const float* __restrict__ beta,
                      float* __restrict__ out)
{
    extern __shared__ char dsm[];
    const uint32_t sb = smem_u32(dsm);
    const int tid  = threadIdx.x;
    const int lane = tid & 31;
    const int wid  = tid >> 5;
    const int wm   = wid & 3;
    const int wn   = wid >> 2;
    const int row0 = blockIdx.x * 128;

    const int ar = tid >> 1, as0 = (tid & 1) * 2;
    const int bn = tid >> 2, bs = tid & 3;

    const uint32_t aOff = (uint32_t)((wm * 32 + (lane & 15)) * 80 + (lane >> 4) * 16);
    const uint32_t bOff = (uint32_t)((wn * 32 + (lane & 7) + ((lane >> 4) << 3)) * 80 +
                                     ((lane >> 3) & 1) * 16);

    float c[2][4][4] = {};

    // prologue: stage 0 = ch0, stage 1 = ch1
    {
#pragma unroll
        for (int pc = 0; pc < 2; ++pc) {
            const uint32_t base = sb + pc * F_STAGE;
            const uint32_t ahi = base, alo = base + F_SZ_A;
            const uint32_t bhi = base + 2 * F_SZ_A, blo = bhi + F_SZ_B;
            const int k0 = pc * 32;
#pragma unroll
            for (int q = 0; q < 2; ++q) {
                int seg = as0 + q;
                CP_ASYNC16(ahi + ar * 80 + seg * 16, g_fh + (size_t)(row0 + ar) * FIN + k0 + seg * 8);
                CP_ASYNC16(alo + ar * 80 + seg * 16, g_fl + (size_t)(row0 + ar) * FIN + k0 + seg * 8);
            }
            CP_ASYNC16(bhi + bn * 80 + bs * 16, g_Wbh + (size_t)bn * FIN + k0 + bs * 8);
            CP_ASYNC16(blo + bn * 80 + bs * 16, g_Wbl + (size_t)bn * FIN + k0 + bs * 8);
            CP_COMMIT();
        }
    }

    int st = 0;
#pragma unroll 1
    for (int ch = 0; ch < FNCH; ++ch) {
        if (ch < FNCH - 1) { CP_WAIT1(); } else { CP_WAIT0(); }
        __syncthreads();
        if (ch + 2 < FNCH) {
            const int st2 = (st >= 1) ? st - 1 : st + 2;
            const int k2 = (ch + 2) * 32;
            const uint32_t base = sb + st2 * F_STAGE;
            const uint32_t ahi = base, alo = base + F_SZ_A;
            const uint32_t bhi = base + 2 * F_SZ_A, blo = bhi + F_SZ_B;
#pragma unroll
            for (int q = 0; q < 2; ++q) {
                int seg = as0 + q;
                CP_ASYNC16(ahi + ar * 80 + seg * 16, g_fh + (size_t)(row0 + ar) * FIN + k2 + seg * 8);
                CP_ASYNC16(alo + ar * 80 + seg * 16, g_fl + (size_t)(row0 + ar) * FIN + k2 + seg * 8);
            }
            CP_ASYNC16(bhi + bn * 80 + bs * 16, g_Wbh + (size_t)bn * FIN + k2 + bs * 8);
            CP_ASYNC16(blo + bn * 80 + bs * 16, g_Wbl + (size_t)bn * FIN + k2 + bs * 8);
            CP_COMMIT();
        }
        {
            const uint32_t aHiB = sb + st * F_STAGE + aOff;
            const uint32_t aLoB = aHiB + F_SZ_A;
            const uint32_t bHiB = sb + st * F_STAGE + 2 * F_SZ_A + bOff;
            const uint32_t bLoB = bHiB + F_SZ_B;
#pragma unroll
            for (int ks = 0; ks < 2; ++ks) {
                const uint32_t ko = ks * 32;
                uint32_t ahr[2][4], bb[4][2];
#pragma unroll
                for (int i = 0; i < 2; ++i)
                    LDSM_X4(ahr[i][0], ahr[i][1], ahr[i][2], ahr[i][3], aHiB + ko + i * 1280);
#pragma unroll
                for (int j2 = 0; j2 < 2; ++j2)
                    LDSM_X4(bb[2 * j2][0], bb[2 * j2][1], bb[2 * j2 + 1][0], bb[2 * j2 + 1][1],
                            bHiB + ko + j2 * 1280);
#pragma unroll
                for (int i = 0; i < 2; ++i)
#pragma unroll
                    for (int j = 0; j < 4; ++j) mma_bf16(c[i][j], ahr[i], bb[j]);

                uint32_t alr[2][4];
#pragma unroll
                for (int i = 0; i < 2; ++i)
                    LDSM_X4(alr[i][0], alr[i][1], alr[i][2], alr[i][3], aLoB + ko + i * 1280);
#pragma unroll
                for (int i = 0; i < 2; ++i)
#pragma unroll
                    for (int j = 0; j < 4; ++j) mma_bf16(c[i][j], alr[i], bb[j]);

#pragma unroll
                for (int j2 = 0; j2 < 2; ++j2)
                    LDSM_X4(bb[2 * j2][0], bb[2 * j2][1], bb[2 * j2 + 1][0], bb[2 * j2 + 1][1],
                            bLoB + ko + j2 * 1280);
#pragma unroll
                for (int i = 0; i < 2; ++i)
#pragma unroll
                    for (int j = 0; j < 4; ++j) mma_bf16(c[i][j], ahr[i], bb[j]);
            }
        }
        st = (st == 2) ? 0 : st + 1;
    }
    __syncthreads();

    float (*Hs)[65] = (float (*)[65])dsm;
    const int colBase = wn * 32 + (lane & 3) * 2;
    const int rowB    = wm * 32 + (lane >> 2);
#pragma unroll
    for (int j = 0; j < 4; ++j) {
        const int col = colBase + j * 8;
        const float b0 = bbv[col], b1 = bbv[col + 1];
#pragma unroll
        for (int i = 0; i < 2; ++i) {
            const int r = rowB + i * 16;
            Hs[r][col]         = c[i][j][0] + b0;
            Hs[r][col + 1]     = c[i][j][1] + b1;
            Hs[r + 8][col]     = c[i][j][2] + b0;
            Hs[r + 8][col + 1] = c[i][j][3] + b1;
        }
    }
    __syncthreads();

    const float g0  = gamma[lane], g1  = gamma[lane + 32];
    const float be0 = beta[lane],  be1 = beta[lane + 32];
#pragma unroll
    for (int rr = 0; rr < 16; ++rr) {
        const int r = wid * 16 + rr;
        float x0 = Hs[r][lane], x1 = Hs[r][lane + 32];
        float s  = x0 + x1;
        float s2 = x0 * x0 + x1 * x1;
#pragma unroll
        for (int o = 16; o > 0; o >>= 1) {
            s  += __shfl_xor_sync(0xffffffffu, s, o);
            s2 += __shfl_xor_sync(0xffffffffu, s2, o);
        }
        float mu  = s * (1.0f / 64.0f);
        float var = s2 * (1.0f / 64.0f) - mu * mu;
        float inv = rsqrtf(var + 1e-5f);
        float y0 = (x0 - mu) * inv * g0 + be0;
        float y1 = (x1 - mu) * inv * g1 + be1;
        out[(size_t)(row0 + r) * 64 + lane]      = fmaxf(y0, 0.0f);
        out[(size_t)(row0 + r) * 64 + lane + 32] = fmaxf(y1, 0.0f);
    }
}

// ============================================================
extern "C" void kernel_launch(void* const* d_in, const int* in_sizes, int n_in,
                              void* d_out, int out_size)
{
    (void)in_sizes; (void)n_in; (void)out_size;
    const float* L0 = (const float*)d_in[0];
    const float* W0 = (const float*)d_in[1];
    const float* b0 = (const float*)d_in[2];
    const float* L1 = (const float*)d_in[3];
    const float* W1 = (const float*)d_in[4];
    const float* b1 = (const float*)d_in[5];
    const float* L2 = (const float*)d_in[6];
    const float* W2 = (const float*)d_in[7];
    const float* b2 = (const float*)d_in[8];
    const float* corr  = (const float*)d_in[9];
    const float* Wb    = (const float*)d_in[10];
    const float* bb    = (const float*)d_in[11];
    const float* gamma = (const float*)d_in[12];
    const float* beta  = (const float*)d_in[13];
    float* out = (float*)d_out;

    cudaFuncSetAttribute(proj_mma_kernel, cudaFuncAttributeMaxDynamicSharedMemorySize, SMEM_PROJ);
    cudaFuncSetAttribute(ccsm_mma_kernel, cudaFuncAttributeMaxDynamicSharedMemorySize, SMEM_CS);
    cudaFuncSetAttribute(attfuse_mma_kernel, cudaFuncAttributeMaxDynamicSharedMemorySize, SMEM_AT);
    cudaFuncSetAttribute(final_mma_kernel, cudaFuncAttributeMaxDynamicSharedMemorySize, SMEM_FIN);

    wconv_kernel<<<dim3(192, 3), 256>>>(W0, W1, W2);
    wbconv_kernel<<<64, 256>>>(Wb);
    cprep_kernel<<<64, 256>>>(corr);
    proj_mma_kernel<<<dim3(256, 3), 256, SMEM_PROJ>>>(L0, L1, L2, b0, b1, b2);
    ccsm_mma_kernel<<<dim3(512, 2), 256, SMEM_CS>>>();
    attfuse_mma_kernel<<<dim3(512, 4), 256, SMEM_AT>>>();
    final_mma_kernel<<<256, 256, SMEM_FIN>>>(bb, gamma, beta, out);
}

// round 17
// speedup vs baseline: 1.0662x; 1.0149x over previous
#include <cuda_runtime.h>
#include <cuda_bf16.h>
#include <cstdint>

// Problem constants
namespace {
constexpr int Bn  = 512;
constexpr int Sn  = 64;
constexpr int En  = 768;
constexpr int Dn  = 256;
constexpr int BS  = Bn * Sn;     // 32768
constexpr int FIN = 1024;        // 2*D*(M-1)
}

// ---- scratch (device globals: allocation-free rule) ----
__device__ float g_proj[3][(size_t)BS * Dn];      // projected modalities [3][B*S, D]
__device__ float g_t[(size_t)BS * Dn];            // anchor @ corr        [B*S, D]
__device__ float g_aT[2][(size_t)Bn * Sn * Sn];   // a_att transposed: [b][j][i]
__device__ float g_o[2][(size_t)Bn * Sn * Sn];    // o_att:            [b][i][j]
__device__ __align__(256) __nv_bfloat16 g_Wh[3 * Dn * En];  // weight hi parts
__device__ __align__(256) __nv_bfloat16 g_Wl[3 * Dn * En];  // weight lo parts
__device__ __align__(256) __nv_bfloat16 g_Ch[Dn * Dn];      // corr^T hi [n][k]
__device__ __align__(256) __nv_bfloat16 g_Cl[Dn * Dn];      // corr^T lo
__device__ __align__(256) __nv_bfloat16 g_fh[(size_t)BS * FIN];  // fused hi
__device__ __align__(256) __nv_bfloat16 g_fl[(size_t)BS * FIN];  // fused lo
__device__ __align__(256) __nv_bfloat16 g_Wbh[64 * FIN];         // Wb hi
__device__ __align__(256) __nv_bfloat16 g_Wbl[64 * FIN];         // Wb lo

// ============================================================
// helpers (baseline PTX only)
// ============================================================
__device__ __forceinline__ uint32_t smem_u32(const void* p) {
    uint32_t a;
    asm("{ .reg .u64 t; cvta.to.shared.u64 t, %1; cvt.u32.u64 %0, t; }" : "=r"(a) : "l"(p));
    return a;
}
#define CP_ASYNC16(dst, src) \
    asm volatile("cp.async.cg.shared.global [%0], [%1], 16;" :: "r"(dst), "l"(src))
#define CP_COMMIT() asm volatile("cp.async.commit_group;" ::: "memory")
#define CP_WAIT0()  asm volatile("cp.async.wait_group 0;" ::: "memory")
#define CP_WAIT1()  asm volatile("cp.async.wait_group 1;" ::: "memory")

#define LDSM_X4(r0, r1, r2, r3, addr) \
    asm volatile("ldmatrix.sync.aligned.m8n8.x4.shared.b16 {%0,%1,%2,%3}, [%4];" \
                 : "=r"(r0), "=r"(r1), "=r"(r2), "=r"(r3) : "r"(addr))

#define LDSM_X4_T(r0, r1, r2, r3, addr) \
    asm volatile("ldmatrix.sync.aligned.m8n8.x4.trans.shared.b16 {%0,%1,%2,%3}, [%4];" \
                 : "=r"(r0), "=r"(r1), "=r"(r2), "=r"(r3) : "r"(addr))

__device__ __forceinline__ void mma_bf16(float* c, const uint32_t* a, const uint32_t* b) {
    asm volatile(
        "mma.sync.aligned.m16n8k16.row.col.f32.bf16.bf16.f32 "
        "{%0,%1,%2,%3}, {%4,%5,%6,%7}, {%8,%9}, {%0,%1,%2,%3};"
        : "+f"(c[0]), "+f"(c[1]), "+f"(c[2]), "+f"(c[3])
        : "r"(a[0]), "r"(a[1]), "r"(a[2]), "r"(a[3]), "r"(b[0]), "r"(b[1]));
}

__device__ __forceinline__ uint32_t pk_bf16x2(float lo, float hi) {
    uint32_t r;
    asm("cvt.rn.bf16x2.f32 %0, %1, %2;" : "=r"(r) : "f"(hi), "f"(lo));
    return r;
}
__device__ __forceinline__ float bf16bits_f(uint32_t b16) { return __uint_as_float(b16 << 16); }

__device__ __forceinline__ void split4(float4 v, uint2& hi, uint2& lo) {
    uint32_t h01 = pk_bf16x2(v.x, v.y);
    uint32_t h23 = pk_bf16x2(v.z, v.w);
    float rx = v.x - bf16bits_f(h01 & 0xffffu);
    float ry = v.y - bf16bits_f(h01 >> 16);
    float rz = v.z - bf16bits_f(h23 & 0xffffu);
    float rw = v.w - bf16bits_f(h23 >> 16);
    hi.x = h01; hi.y = h23;
    lo.x = pk_bf16x2(rx, ry);
    lo.y = pk_bf16x2(rz, rw);
}

__device__ __forceinline__ void split1(float v, __nv_bfloat16* hp, __nv_bfloat16* lp) {
    __nv_bfloat16 h = __float2bfloat16(v);
    *hp = h;
    *lp = __float2bfloat16(v - __bfloat162float(h));
}

// ============================================================
// Kernel B (merged prep): weight/Wb/corr^T splits in ONE launch.
// blocks 0..575: W0/W1/W2; 576..639: Wb; 640..703: corr^T
// ============================================================
__global__ __launch_bounds__(256) void prep_kernel(
    const float* __restrict__ W0, const float* __restrict__ W1, const float* __restrict__ W2,
    const float* __restrict__ Wb, const float* __restrict__ corr)
{
    __shared__ float tile[32][33];
    const int blk = blockIdx.x;
    if (blk < 576) {
        const int m = blk / 192;
        const int bx = blk % 192;
        const float* W = (m == 0) ? W0 : (m == 1) ? W1 : W2;
        const size_t base = (size_t)m * Dn * En;
        int idx = (bx * 256 + threadIdx.x) * 4;
        float4 v = *(const float4*)(W + idx);
        uint2 hi, lo;
        split4(v, hi, lo);
        *(uint2*)(g_Wh + base + idx) = hi;
        *(uint2*)(g_Wl + base + idx) = lo;
    } else if (blk < 640) {
        int idx = ((blk - 576) * 256 + threadIdx.x) * 4;
        float4 v = *(const float4*)(Wb + idx);
        uint2 hi, lo;
        split4(v, hi, lo);
        *(uint2*)(g_Wbh + idx) = hi;
        *(uint2*)(g_Wbl + idx) = lo;
    } else {
        const int bx = blk - 640;
        const int n0 = (bx & 7) * 32;
        const int k0 = (bx >> 3) * 32;
        const int tr = threadIdx.x >> 5, tc = threadIdx.x & 31;
        for (int r = tr; r < 32; r += 8)
            tile[r][tc] = corr[(size_t)(k0 + r) * Dn + n0 + tc];
        __syncthreads();
        for (int r = tr; r < 32; r += 8) {
            float v = tile[tc][r];
            split1(v, &g_Ch[(size_t)(n0 + r) * Dn + k0 + tc],
                      &g_Cl[(size_t)(n0 + r) * Dn + k0 + tc]);
        }
    }
}

// ============================================================
// Kernel C: HMMA projection GEMM, 256 threads / 8 warps (2M x 4N),
// warp tile 64x64, 3-stage cp.async pipeline. K=768, z in {0,1,2}.
// z==0 additionally computes g_t = tile @ corrT^T (fused tmat).
// ============================================================
namespace {
constexpr int NCHUNK = En / 32;                 // 24
constexpr uint32_t SZ_A  = 128 * 80;            // 10240
constexpr uint32_t SZ_B  = 256 * 80;            // 20480
constexpr uint32_t STAGE = 2 * SZ_A + 2 * SZ_B; // 61440
constexpr uint32_t TD_HI = 0;                   // 8 chunks x 10240
constexpr uint32_t TD_LO = 81920;
constexpr uint32_t TD_B  = 163840;              // 2 stages x 20480
constexpr uint32_t SMEM_PROJ = 204800;
}

__global__ __launch_bounds__(256, 1)
void proj_mma_kernel(const float* __restrict__ L0, const float* __restrict__ L1,
                     const float* __restrict__ L2,
                     const float* __restrict__ P0, const float* __restrict__ P1,
                     const float* __restrict__ P2)
{
    extern __shared__ char dsm[];
    const uint32_t sb = smem_u32(dsm);
    const int tid  = threadIdx.x;
    const int lane = tid & 31;
    const int wid  = tid >> 5;
    const int wm   = wid & 1;
    const int wn   = wid >> 1;
    const int z    = blockIdx.y;
    const int row0 = blockIdx.x * 128;

    const float* A = (z == 1) ? L1 : (z == 2) ? L2 : L0;
    const __nv_bfloat16* Wh = g_Wh + (size_t)z * Dn * En;
    const __nv_bfloat16* Wl = g_Wl + (size_t)z * Dn * En;

    const int bn   = tid >> 2;
    const int bseg = tid & 3;
    const int ar = tid >> 1;
    const int ah = tid & 1;

    float4 af[4];

    const uint32_t aOff = (uint32_t)((wm * 64 + (lane & 15)) * 80 + (lane >> 4) * 16);
    const uint32_t bOff = (uint32_t)((wn * 64 + (lane & 7) + ((lane >> 4) << 3)) * 80 +
                                     ((lane >> 3) & 1) * 16);

    float c[4][8][4] = {};

    {
#pragma unroll
        for (int pc = 0; pc < 2; ++pc) {
            const uint32_t bhi = sb + pc * STAGE + 2 * SZ_A;
            const uint32_t blo = bhi + SZ_B;
            const int k0 = pc * 32;
#pragma unroll
            for (int r = 0; r < 4; ++r) {
                int row = bn + r * 64;
                CP_ASYNC16(bhi + row * 80 + bseg * 16, Wh + (size_t)row * 768 + k0 + bseg * 8);
                CP_ASYNC16(blo + row * 80 + bseg * 16, Wl + (size_t)row * 768 + k0 + bseg * 8);
            }
            CP_COMMIT();
        }
        const float* p = A + (size_t)(row0 + ar) * 768 + ah * 16;
        af[0] = *(const float4*)(p);
        af[1] = *(const float4*)(p + 4);
        af[2] = *(const float4*)(p + 8);
        af[3] = *(const float4*)(p + 12);
    }

    int st = 0;
#pragma unroll 1
    for (int ch = 0; ch < NCHUNK; ++ch) {
        {
            char* ahi = dsm + st * STAGE;
            char* alo = ahi + SZ_A;
            const uint32_t off = (uint32_t)(ar * 80 + ah * 32);
#pragma unroll
            for (int q = 0; q < 4; ++q) {
                uint2 hi, lo;
                split4(af[q], hi, lo);
                *(uint2*)(ahi + off + q * 8) = hi;
                *(uint2*)(alo + off + q * 8) = lo;
            }
        }
        if (ch < NCHUNK - 1) {
            const float* p = A + (size_t)(row0 + ar) * 768 + (ch + 1) * 32 + ah * 16;
            af[0] = *(const float4*)(p);
            af[1] = *(const float4*)(p + 4);
            af[2] = *(const float4*)(p + 8);
            af[3] = *(const float4*)(p + 12);
        }
        if (ch < NCHUNK - 1) { CP_WAIT1(); } else { CP_WAIT0(); }
        __syncthreads();
        if (ch + 2 < NCHUNK) {
            const int st2 = (st >= 1) ? st - 1 : st + 2;
            const int k2 = (ch + 2) * 32;
            const uint32_t bhi = sb + st2 * STAGE + 2 * SZ_A;
            const uint32_t blo = bhi + SZ_B;
#pragma unroll
            for (int r = 0; r < 4; ++r) {
                int row = bn + r * 64;
                CP_ASYNC16(bhi + row * 80 + bseg * 16, Wh + (size_t)row * 768 + k2 + bseg * 8);
                CP_ASYNC16(blo + row * 80 + bseg * 16, Wl + (size_t)row * 768 + k2 + bseg * 8);
            }
            CP_COMMIT();
        }
        {
            const uint32_t aHiB = sb + st * STAGE + aOff;
            const uint32_t aLoB = aHiB + SZ_A;
            const uint32_t bHiB = sb + st * STAGE + 2 * SZ_A + bOff;
            const uint32_t bLoB = bHiB + SZ_B;
#pragma unroll
            for (int ks = 0; ks < 2; ++ks) {
                const uint32_t ko = ks * 32;
                uint32_t ahr[4][4], bb[8][2];
#pragma unroll
                for (int i = 0; i < 4; ++i)
                    LDSM_X4(ahr[i][0], ahr[i][1], ahr[i][2], ahr[i][3], aHiB + ko + i * 1280);
#pragma unroll
                for (int j2 = 0; j2 < 4; ++j2)
                    LDSM_X4(bb[2 * j2][0], bb[2 * j2][1], bb[2 * j2 + 1][0], bb[2 * j2 + 1][1],
                            bHiB + ko + j2 * 1280);
#pragma unroll
                for (int i = 0; i < 4; ++i)
#pragma unroll
                    for (int j = 0; j < 8; ++j) mma_bf16(c[i][j], ahr[i], bb[j]);

                uint32_t alr[4][4];
#pragma unroll
                for (int i = 0; i < 4; ++i)
                    LDSM_X4(alr[i][0], alr[i][1], alr[i][2], alr[i][3], aLoB + ko + i * 1280);
#pragma unroll
                for (int i = 0; i < 4; ++i)
#pragma unroll
                    for (int j = 0; j < 8; ++j) mma_bf16(c[i][j], alr[i], bb[j]);

#pragma unroll
                for (int j2 = 0; j2 < 4; ++j2)
                    LDSM_X4(bb[2 * j2][0], bb[2 * j2][1], bb[2 * j2 + 1][0], bb[2 * j2 + 1][1],
                            bLoB + ko + j2 * 1280);
#pragma unroll
                for (int i = 0; i < 4; ++i)
#pragma unroll
                    for (int j = 0; j < 8; ++j) mma_bf16(c[i][j], ahr[i], bb[j]);
            }
        }
        st = (st == 2) ? 0 : st + 1;
    }

    const float* bias = (z == 0) ? P0 : (z == 1) ? P1 : P2;
    float* Cout = g_proj[z];
    const int colBase = wn * 64 + (lane & 3) * 2;
    const int rowBase = row0 + wm * 64 + (lane >> 2);
#pragma unroll
    for (int j = 0; j < 8; ++j) {
        const int col = colBase + j * 8;
        const float b0 = bias[col], b1 = bias[col + 1];
#pragma unroll
        for (int i = 0; i < 4; ++i) {
            const int r = rowBase + i * 16;
            float2 lo2 = make_float2(c[i][j][0] + b0, c[i][j][1] + b1);
            float2 hi2 = make_float2(c[i][j][2] + b0, c[i][j][3] + b1);
            *(float2*)(Cout + (size_t)r * 256 + col)       = lo2;
            *(float2*)(Cout + (size_t)(r + 8) * 256 + col) = hi2;
        }
    }

    if (z != 0) return;

    // ================= fused tmat (z==0 only) =================
    __syncthreads();
    {
        const int lr = wm * 64 + (lane >> 2);
#pragma unroll
        for (int j = 0; j < 8; ++j) {
            const int col = colBase + j * 8;
            const float b0 = bias[col], b1 = bias[col + 1];
            const int kc = col >> 5, c32 = col & 31;
#pragma unroll
            for (int i = 0; i < 4; ++i) {
#pragma unroll
                for (int half = 0; half < 2; ++half) {
                    const int r = lr + i * 16 + half * 8;
                    float v0 = c[i][j][half * 2 + 0] + b0;
                    float v1 = c[i][j][half * 2 + 1] + b1;
                    uint32_t hh = pk_bf16x2(v0, v1);
                    float q0 = v0 - bf16bits_f(hh & 0xffffu);
                    float q1 = v1 - bf16bits_f(hh >> 16);
                    uint32_t ll = pk_bf16x2(q0, q1);
                    *(uint32_t*)(dsm + TD_HI + kc * 10240 + r * 80 + c32 * 2) = hh;
                    *(uint32_t*)(dsm + TD_LO + kc * 10240 + r * 80 + c32 * 2) = ll;
                }
            }
        }
    }
    const int tbrow = tid >> 1;
    const int tbs   = (tid & 1) * 2;
    {
        const uint32_t bhi = sb + TD_B;
        const uint32_t blo = bhi + 10240;
#pragma unroll
        for (int s = 0; s < 2; ++s) {
            int seg = tbs + s;
            CP_ASYNC16(bhi + tbrow * 80 + seg * 16, g_Ch + (size_t)tbrow * 256 + seg * 8);
            CP_ASYNC16(blo + tbrow * 80 + seg * 16, g_Cl + (size_t)tbrow * 256 + seg * 8);
        }
        CP_COMMIT();
    }

    const uint32_t a2off = (uint32_t)((wm * 64 + (lane & 15)) * 80 + (lane >> 4) * 16);
    const uint32_t b2off = (uint32_t)((wn * 32 + (lane & 7) + ((lane >> 4) << 3)) * 80 +
                                      ((lane >> 3) & 1) * 16);
    float c2[4][4][4] = {};

#pragma unroll 1
    for (int it = 0; it < 16; ++it) {
        const int stg = it & 1;
        const int nh = it >> 3, kc = it & 7;
        CP_WAIT0();
        __syncthreads();
        if (it < 15) {
            const int nh1 = (it + 1) >> 3, kc1 = (it + 1) & 7;
            const uint32_t bhi = sb + TD_B + (stg ^ 1) * 20480;
            const uint32_t blo = bhi + 10240;
#pragma unroll
            for (int s = 0; s < 2; ++s) {
                int seg = tbs + s;
                CP_ASYNC16(bhi + tbrow * 80 + seg * 16,
                           g_Ch + (size_t)(nh1 * 128 + tbrow) * 256 + kc1 * 32 + seg * 8);
                CP_ASYNC16(blo + tbrow * 80 + seg * 16,
                           g_Cl + (size_t)(nh1 * 128 + tbrow) * 256 + kc1 * 32 + seg * 8);
            }
            CP_COMMIT();
        }
        {
            const uint32_t aHiB = sb + TD_HI + kc * 10240 + a2off;
            const uint32_t aLoB = aHiB + (TD_LO - TD_HI);
            const uint32_t bHiB = sb + TD_B + stg * 20480 + b2off;
            const uint32_t bLoB = bHiB + 10240;
#pragma unroll
            for (int ks = 0; ks < 2; ++ks) {
                const uint32_t ko = ks * 32;
                uint32_t ahr[4][4], bb[4][2];
#pragma unroll
                for (int i = 0; i < 4; ++i)
                    LDSM_X4(ahr[i][0], ahr[i][1], ahr[i][2], ahr[i][3], aHiB + ko + i * 1280);
#pragma unroll
                for (int j2 = 0; j2 < 2; ++j2)
                    LDSM_X4(bb[2 * j2][0], bb[2 * j2][1], bb[2 * j2 + 1][0], bb[2 * j2 + 1][1],
                            bHiB + ko + j2 * 1280);
#pragma unroll
                for (int i = 0; i < 4; ++i)
#pragma unroll
                    for (int j = 0; j < 4; ++j) mma_bf16(c2[i][j], ahr[i], bb[j]);

                uint32_t alr[4][4];
#pragma unroll
                for (int i = 0; i < 4; ++i)
                    LDSM_X4(alr[i][0], alr[i][1], alr[i][2], alr[i][3], aLoB + ko + i * 1280);
#pragma unroll
                for (int i = 0; i < 4; ++i)
#pragma unroll
                    for (int j = 0; j < 4; ++j) mma_bf16(c2[i][j], alr[i], bb[j]);

#pragma unroll
                for (int j2 = 0; j2 < 2; ++j2)
                    LDSM_X4(bb[2 * j2][0], bb[2 * j2][1], bb[2 * j2 + 1][0], bb[2 * j2 + 1][1],
                            bLoB + ko + j2 * 1280);
#pragma unroll
                for (int i = 0; i < 4; ++i)
#pragma unroll
                    for (int j = 0; j < 4; ++j) mma_bf16(c2[i][j], ahr[i], bb[j]);
            }
        }
        if (kc == 7) {
            const int colB2 = nh * 128 + wn * 32 + (lane & 3) * 2;
#pragma unroll
            for (int j = 0; j < 4; ++j) {
                const int col = colB2 + j * 8;
#pragma unroll
                for (int i = 0; i < 4; ++i) {
                    const int r = rowBase + i * 16;
                    float2 lo2 = make_float2(c2[i][j][0], c2[i][j][1]);
                    float2 hi2 = make_float2(c2[i][j][2], c2[i][j][3]);
                    *(float2*)(g_t + (size_t)r * 256 + col)       = lo2;
                    *(float2*)(g_t + (size_t)(r + 8) * 256 + col) = hi2;
                }
            }
#pragma unroll
            for (int i = 0; i < 4; ++i)
#pragma unroll
                for (int j = 0; j < 4; ++j)
#pragma unroll
                    for (int q = 0; q < 4; ++q) c2[i][j][q] = 0.f;
        }
    }
}

// ============================================================
// Kernel 3 (HMMA): per (b,p): cc = T @ O^T via mma.sync (bf16 split),
// dual softmax in smem.
// ============================================================
namespace {
constexpr uint32_t CS_TH = 0;                      // 64 x 144B
constexpr uint32_t CS_TL = 64 * 144;               // 9216
constexpr uint32_t CS_OH = 2 * 64 * 144;           // 18432
constexpr uint32_t CS_OL = 3 * 64 * 144;           // 27648
constexpr uint32_t CS_SC = 4 * 64 * 144;           // 36864 (floats [64][65])
constexpr uint32_t SMEM_CS = CS_SC + 64 * 65 * 4;  // 53504
}

__global__ __launch_bounds__(256) void ccsm_mma_kernel()
{
    extern __shared__ char dsm[];
    const uint32_t sb = smem_u32(dsm);
    const int b = blockIdx.x;
    const int p = blockIdx.y;
    const float* T = g_t + (size_t)b * Sn * Dn;
    const float* O = g_proj[p + 1] + (size_t)b * Sn * Dn;

    const int tid = threadIdx.x;
    const int lane = tid & 31;
    const int wid  = tid >> 5;
    const int wm   = wid & 1;
    const int wn   = wid >> 1;

    const uint32_t aBase = sb + CS_TH +
        (uint32_t)((wm * 32 + (lane & 15)) * 144 + (lane >> 4) * 16);
    const uint32_t bBase = sb + CS_OH +
        (uint32_t)((wn * 16 + (lane & 7) + ((lane >> 4) << 3)) * 144 + ((lane >> 3) & 1) * 16);

    float c[2][2][4] = {};

#pragma unroll 1
    for (int kc = 0; kc < 4; ++kc) {
        {
            char* th = dsm + CS_TH; char* tl = dsm + CS_TL;
            char* oh = dsm + CS_OH; char* ol = dsm + CS_OL;
#pragma unroll
            for (int q = 0; q < 4; ++q) {
                int idx = (q * 256 + tid) * 4;
                int r = idx >> 6, c0 = idx & 63;
                float4 vT = *(const float4*)(T + (size_t)r * 256 + kc * 64 + c0);
                float4 vO = *(const float4*)(O + (size_t)r * 256 + kc * 64 + c0);
                uint2 h, l;
                split4(vT, h, l);
                *(uint2*)(th + r * 144 + c0 * 2) = h;
                *(uint2*)(tl + r * 144 + c0 * 2) = l;
                split4(vO, h, l);
                *(uint2*)(oh + r * 144 + c0 * 2) = h;
                *(uint2*)(ol + r * 144 + c0 * 2) = l;
            }
        }
        __syncthreads();
#pragma unroll
        for (int ks = 0; ks < 4; ++ks) {
            const uint32_t ko = (uint32_t)(ks * 32);
            uint32_t ahr[2][4], bb[2][2];
#pragma unroll
            for (int i = 0; i < 2; ++i)
                LDSM_X4(ahr[i][0], ahr[i][1], ahr[i][2], ahr[i][3], aBase + ko + i * 16 * 144);
            LDSM_X4(bb[0][0], bb[0][1], bb[1][0], bb[1][1], bBase + ko);
#pragma unroll
            for (int i = 0; i < 2; ++i)
#pragma unroll
                for (int j = 0; j < 2; ++j) mma_bf16(c[i][j], ahr[i], bb[j]);

            uint32_t alr[2][4];
#pragma unroll
            for (int i = 0; i < 2; ++i)
                LDSM_X4(alr[i][0], alr[i][1], alr[i][2], alr[i][3],
                        aBase + (CS_TL - CS_TH) + ko + i * 16 * 144);
#pragma unroll
            for (int i = 0; i < 2; ++i)
#pragma unroll
                for (int j = 0; j < 2; ++j) mma_bf16(c[i][j], alr[i], bb[j]);

            uint32_t bl[2][2];
            LDSM_X4(bl[0][0], bl[0][1], bl[1][0], bl[1][1], bBase + (CS_OL - CS_OH) + ko);
#pragma unroll
            for (int i = 0; i < 2; ++i)
#pragma unroll
                for (int j = 0; j < 2; ++j) mma_bf16(c[i][j], ahr[i], bl[j]);
        }
        __syncthreads();
    }

    float* sc = (float*)(dsm + CS_SC);
    {
        const int rowB = wm * 32 + (lane >> 2);
        const int colB = wn * 16 + (lane & 3) * 2;
#pragma unroll
        for (int i = 0; i < 2; ++i)
#pragma unroll
            for (int j = 0; j < 2; ++j) {
                sc[(rowB + i * 16)     * 65 + colB + j * 8]     = c[i][j][0];
                sc[(rowB + i * 16)     * 65 + colB + j * 8 + 1] = c[i][j][1];
                sc[(rowB + i * 16 + 8) * 65 + colB + j * 8]     = c[i][j][2];
                sc[(rowB + i * 16 + 8) * 65 + colB + j * 8 + 1] = c[i][j][3];
            }
    }
    __syncthreads();

    const int warp = wid, lane2 = lane;
    float* orow  = g_o[p]  + (size_t)b * Sn * Sn;
    float* aTrow = g_aT[p] + (size_t)b * Sn * Sn;

    for (int r = warp; r < 64; r += 8) {
        float x0 = sc[r * 65 + lane2], x1 = sc[r * 65 + lane2 + 32];
        float mx = fmaxf(x0, x1);
#pragma unroll
        for (int o = 16; o > 0; o >>= 1) mx = fmaxf(mx, __shfl_xor_sync(0xffffffffu, mx, o));
        float e0 = __expf(x0 - mx), e1 = __expf(x1 - mx);
        float s = e0 + e1;
#pragma unroll
        for (int o = 16; o > 0; o >>= 1) s += __shfl_xor_sync(0xffffffffu, s, o);
        float inv = 1.0f / s;
        orow[r * 64 + lane2]      = e0 * inv;
        orow[r * 64 + lane2 + 32] = e1 * inv;
    }
    for (int cix = warp; cix < 64; cix += 8) {
        float x0 = sc[lane2 * 65 + cix], x1 = sc[(lane2 + 32) * 65 + cix];
        float mx = fmaxf(x0, x1);
#pragma unroll
        for (int o = 16; o > 0; o >>= 1) mx = fmaxf(mx, __shfl_xor_sync(0xffffffffu, mx, o));
        float e0 = __expf(x0 - mx), e1 = __expf(x1 - mx);
        float s = e0 + e1;
#pragma unroll
        for (int o = 16; o > 0; o >>= 1) s += __shfl_xor_sync(0xffffffffu, s, o);
        float inv = 1.0f / s;
        aTrow[cix * 64 + lane2]      = e0 * inv;
        aTrow[cix * 64 + lane2 + 32] = e1 * inv;
    }
}

// ============================================================
// Kernel 4 (HMMA): att GEMM + residual -> fused bf16 hi/lo.
// X processed in two 128-col halves: smem 53 KB -> higher occupancy.
// ============================================================
namespace {
constexpr uint32_t A2_A_H = 0;                       // 64 rows x 144B
constexpr uint32_t A2_A_L = 64 * 144;                // 9216
constexpr uint32_t A2_X_H = 2 * 64 * 144;            // 18432; 64 rows x 272B
constexpr uint32_t A2_X_L = A2_X_H + 64 * 272;       // 35840
constexpr uint32_t SMEM_AT = A2_X_L + 64 * 272;      // 53248
}

__global__ __launch_bounds__(256)
void attfuse_mma_kernel()
{
    extern __shared__ char dsm[];
    const uint32_t sb = smem_u32(dsm);
    const int b    = blockIdx.x;
    const int p    = blockIdx.y >> 1;
    const int side = blockIdx.y & 1;
    const int tid  = threadIdx.x;
    const int lane = tid & 31;
    const int wid  = tid >> 5;
    const int wm   = wid & 1;        // 2 warps in M
    const int wn   = wid >> 1;       // 4 warps in N (32 cols each per half)

    const float* Mat = (side == 0) ? (g_aT[p] + (size_t)b * 4096)
                                   : (g_o[p]  + (size_t)b * 4096);
    const float* X   = (side == 0) ? (g_proj[0]     + (size_t)b * Sn * Dn)
                                   : (g_proj[p + 1] + (size_t)b * Sn * Dn);

    // ---- stage A (64x64 fp32 -> hi/lo bf16, stride 144B) ----
    {
        char* ahp = dsm + A2_A_H;
        char* alp = dsm + A2_A_L;
#pragma unroll
        for (int q = 0; q < 4; ++q) {
            int idx = (q * 256 + tid) * 4;
            float4 v = *(const float4*)(Mat + idx);
            int r = idx >> 6, c0 = idx & 63;
            uint2 hi, lo;
            split4(v, hi, lo);
            *(uint2*)(ahp + r * 144 + c0 * 2) = hi;
            *(uint2*)(alp + r * 144 + c0 * 2) = lo;
        }
    }

    const uint32_t aHiB = sb + A2_A_H + (uint32_t)((wm * 32 + (lane & 15)) * 144 + (lane >> 4) * 16);
    const uint32_t aLoB = aHiB + (A2_A_L - A2_A_H);
    const uint32_t bHiB = sb + A2_X_H + (uint32_t)((lane & 15) * 272 + (wn * 32 + (lane >> 4) * 8) * 2);
    const uint32_t bLoB = bHiB + (A2_X_L - A2_X_H);

    const char* xhp = dsm + A2_X_H;
    const char* xlp = dsm + A2_X_L;
    const int rowBase = wm * 32 + (lane >> 2);
    const int colBaseW = wn * 32 + (lane & 3) * 2;
    const size_t dstBase0 = (size_t)(b * 64) * FIN + p * 512 + side * 256;

#pragma unroll 1
    for (int hf = 0; hf < 2; ++hf) {
        // ---- stage X half (64 rows x 128 cols fp32 -> hi/lo bf16, stride 272B) ----
        {
            char* xh = dsm + A2_X_H;
            char* xl = dsm + A2_X_L;
#pragma unroll
            for (int q = 0; q < 8; ++q) {
                int idx = (q * 256 + tid) * 4;       // 8192 floats
                int r = idx >> 7, c0 = idx & 127;
                float4 v = *(const float4*)(X + (size_t)r * 256 + hf * 128 + c0);
                uint2 hi, lo;
                split4(v, hi, lo);
                *(uint2*)(xh + r * 272 + c0 * 2) = hi;
                *(uint2*)(xl + r * 272 + c0 * 2) = lo;
            }
        }
        __syncthreads();

        float c[2][4][4] = {};
#pragma unroll 1
        for (int ks = 0; ks < 4; ++ks) {
            const uint32_t ak = (uint32_t)(ks * 32);
            const uint32_t bk = (uint32_t)(ks * 16 * 272);
            uint32_t ahr[2][4], bb[4][2];
#pragma unroll
            for (int i = 0; i < 2; ++i)
                LDSM_X4(ahr[i][0], ahr[i][1], ahr[i][2], ahr[i][3], aHiB + ak + i * 16 * 144);
#pragma unroll
            for (int j2 = 0; j2 < 2; ++j2)
                LDSM_X4_T(bb[2 * j2][0], bb[2 * j2][1], bb[2 * j2 + 1][0], bb[2 * j2 + 1][1],
                          bHiB + bk + j2 * 32);
#pragma unroll
            for (int i = 0; i < 2; ++i)
#pragma unroll
                for (int j = 0; j < 4; ++j) mma_bf16(c[i][j], ahr[i], bb[j]);

            uint32_t alr[2][4];
#pragma unroll
            for (int i = 0; i < 2; ++i)
                LDSM_X4(alr[i][0], alr[i][1], alr[i][2], alr[i][3], aLoB + ak + i * 16 * 144);
#pragma unroll
            for (int i = 0; i < 2; ++i)
#pragma unroll
                for (int j = 0; j < 4; ++j) mma_bf16(c[i][j], alr[i], bb[j]);

#pragma unroll
            for (int j2 = 0; j2 < 2; ++j2)
                LDSM_X4_T(bb[2 * j2][0], bb[2 * j2][1], bb[2 * j2 + 1][0], bb[2 * j2 + 1][1],
                          bLoB + bk + j2 * 32);
#pragma unroll
            for (int i = 0; i < 2; ++i)
#pragma unroll
                for (int j = 0; j < 4; ++j) mma_bf16(c[i][j], ahr[i], bb[j]);
        }

        // ---- epilogue half: residual from smem, split, store ----
#pragma unroll
        for (int i = 0; i < 2; ++i) {
#pragma unroll
            for (int j = 0; j < 4; ++j) {
                const int col = colBaseW + j * 8;
#pragma unroll
                for (int half2 = 0; half2 < 2; ++half2) {
                    const int r = rowBase + i * 16 + half2 * 8;
                    uint32_t rh = *(const uint32_t*)(xhp + r * 272 + col * 2);
                    uint32_t rl = *(const uint32_t*)(xlp + r * 272 + col * 2);
                    float res0 = bf16bits_f(rh & 0xffffu) + bf16bits_f(rl & 0xffffu);
                    float res1 = bf16bits_f(rh >> 16)     + bf16bits_f(rl >> 16);
                    float v0 = c[i][j][half2 * 2 + 0] + res0;
                    float v1 = c[i][j][half2 * 2 + 1] + res1;
                    uint32_t hh = pk_bf16x2(v0, v1);
                    float q0 = v0 - bf16bits_f(hh & 0xffffu);
                    float q1 = v1 - bf16bits_f(hh >> 16);
                    uint32_t ll = pk_bf16x2(q0, q1);
                    size_t e = dstBase0 + (size_t)r * FIN + hf * 128 + col;
                    *(uint32_t*)(g_fh + e) = hh;
                    *(uint32_t*)(g_fl + e) = ll;
                }
            }
        }
        __syncthreads();   // epilogue reads done before restaging X
    }
}

// ============================================================
// Kernel 5: HMMA final: h = fused @ Wb^T + bb; LayerNorm(64); ReLU
// 3-stage cp.async pipeline (wait_group 1), 2 CTAs/SM.
// ============================================================
namespace {
constexpr int FNCH = FIN / 32;                    // 32
constexpr uint32_t F_SZ_A = 128 * 80;             // 10240
constexpr uint32_t F_SZ_B = 64 * 80;              // 5120
constexpr uint32_t F_STAGE = 2 * F_SZ_A + 2 * F_SZ_B;  // 30720
constexpr uint32_t SMEM_FIN = 3 * F_STAGE;        // 92160
}

__global__ __launch_bounds__(256, 2)
void final_mma_kernel(const float* __restrict__ bbv,
                      const float* __restrict__ gamma, const float* __restrict__ beta,
                      float* __restrict__ out)
{
    extern __shared__ char dsm[];
    const uint32_t sb = smem_u32(dsm);
    const int tid  = threadIdx.x;
    const int lane = tid & 31;
    const int wid  = tid >> 5;
    const int wm   = wid & 3;
    const int wn   = wid >> 2;
    const int row0 = blockIdx.x * 128;

    const int ar = tid >> 1, as0 = (tid & 1) * 2;
    const int bn = tid >> 2, bs = tid & 3;

    const uint32_t aOff = (uint32_t)((wm * 32 + (lane & 15)) * 80 + (lane >> 4) * 16);
    const uint32_t bOff = (uint32_t)((wn * 32 + (lane & 7) + ((lane >> 4) << 3)) * 80 +
                                     ((lane >> 3) & 1) * 16);

    float c[2][4][4] = {};

    {
#pragma unroll
        for (int pc = 0; pc < 2; ++pc) {
            const uint32_t base = sb + pc * F_STAGE;
            const uint32_t ahi = base, alo = base + F_SZ_A;
            const uint32_t bhi = base + 2 * F_SZ_A, blo = bhi + F_SZ_B;
            const int k0 = pc * 32;
#pragma unroll
            for (int q = 0; q < 2; ++q) {
                int seg = as0 + q;
                CP_ASYNC16(ahi + ar * 80 + seg * 16, g_fh + (size_t)(row0 + ar) * FIN + k0 + seg * 8);
                CP_ASYNC16(alo + ar * 80 + seg * 16, g_fl + (size_t)(row0 + ar) * FIN + k0 + seg * 8);
            }
            CP_ASYNC16(bhi + bn * 80 + bs * 16, g_Wbh + (size_t)bn * FIN + k0 + bs * 8);
            CP_ASYNC16(blo + bn * 80 + bs * 16, g_Wbl + (size_t)bn * FIN + k0 + bs * 8);
            CP_COMMIT();
        }
    }

    int st = 0;
#pragma unroll 1
    for (int ch = 0; ch < FNCH; ++ch) {
        if (ch < FNCH - 1) { CP_WAIT1(); } else { CP_WAIT0(); }
        __syncthreads();
        if (ch + 2 < FNCH) {
            const int st2 = (st >= 1) ? st - 1 : st + 2;
            const int k2 = (ch + 2) * 32;
            const uint32_t base = sb + st2 * F_STAGE;
            const uint32_t ahi = base, alo = base + F_SZ_A;
            const uint32_t bhi = base + 2 * F_SZ_A, blo = bhi + F_SZ_B;
#pragma unroll
            for (int q = 0; q < 2; ++q) {
                int seg = as0 + q;
                CP_ASYNC16(ahi + ar * 80 + seg * 16, g_fh + (size_t)(row0 + ar) * FIN + k2 + seg * 8);
                CP_ASYNC16(alo + ar * 80 + seg * 16, g_fl + (size_t)(row0 + ar) * FIN + k2 + seg * 8);
            }
            CP_ASYNC16(bhi + bn * 80 + bs * 16, g_Wbh + (size_t)bn * FIN + k2 + bs * 8);
            CP_ASYNC16(blo + bn * 80 + bs * 16, g_Wbl + (size_t)bn * FIN + k2 + bs * 8);
            CP_COMMIT();
        }
        {
            const uint32_t aHiB = sb + st * F_STAGE + aOff;
            const uint32_t aLoB = aHiB + F_SZ_A;
            const uint32_t bHiB = sb + st * F_STAGE + 2 * F_SZ_A + bOff;
            const uint32_t bLoB = bHiB + F_SZ_B;
#pragma unroll
            for (int ks = 0; ks < 2; ++ks) {
                const uint32_t ko = ks * 32;
                uint32_t ahr[2][4], bb[4][2];
#pragma unroll
                for (int i = 0; i < 2; ++i)
                    LDSM_X4(ahr[i][0], ahr[i][1], ahr[i][2], ahr[i][3], aHiB + ko + i * 1280);
#pragma unroll
                for (int j2 = 0; j2 < 2; ++j2)
                    LDSM_X4(bb[2 * j2][0], bb[2 * j2][1], bb[2 * j2 + 1][0], bb[2 * j2 + 1][1],
                            bHiB + ko + j2 * 1280);
#pragma unroll
                for (int i = 0; i < 2; ++i)
#pragma unroll
                    for (int j = 0; j < 4; ++j) mma_bf16(c[i][j], ahr[i], bb[j]);

                uint32_t alr[2][4];
#pragma unroll
                for (int i = 0; i < 2; ++i)
                    LDSM_X4(alr[i][0], alr[i][1], alr[i][2], alr[i][3], aLoB + ko + i * 1280);
#pragma unroll
                for (int i = 0; i < 2; ++i)
#pragma unroll
                    for (int j = 0; j < 4; ++j) mma_bf16(c[i][j], alr[i], bb[j]);

#pragma unroll
                for (int j2 = 0; j2 < 2; ++j2)
                    LDSM_X4(bb[2 * j2][0], bb[2 * j2][1], bb[2 * j2 + 1][0], bb[2 * j2 + 1][1],
                            bLoB + ko + j2 * 1280);
#pragma unroll
                for (int i = 0; i < 2; ++i)
#pragma unroll
                    for (int j = 0; j < 4; ++j) mma_bf16(c[i][j], ahr[i], bb[j]);
            }
        }
        st = (st == 2) ? 0 : st + 1;
    }
    __syncthreads();

    float (*Hs)[65] = (float (*)[65])dsm;
    const int colBase = wn * 32 + (lane & 3) * 2;
    const int rowB    = wm * 32 + (lane >> 2);
#pragma unroll
    for (int j = 0; j < 4; ++j) {
        const int col = colBase + j * 8;
        const float b0 = bbv[col], b1 = bbv[col + 1];
#pragma unroll
        for (int i = 0; i < 2; ++i) {
            const int r = rowB + i * 16;
            Hs[r][col]         = c[i][j][0] + b0;
            Hs[r][col + 1]     = c[i][j][1] + b1;
            Hs[r + 8][col]     = c[i][j][2] + b0;
            Hs[r + 8][col + 1] = c[i][j][3] + b1;
        }
    }
    __syncthreads();

    const float g0  = gamma[lane], g1  = gamma[lane + 32];
    const float be0 = beta[lane],  be1 = beta[lane + 32];
#pragma unroll
    for (int rr = 0; rr < 16; ++rr) {
        const int r = wid * 16 + rr;
        float x0 = Hs[r][lane], x1 = Hs[r][lane + 32];
        float s  = x0 + x1;
        float s2 = x0 * x0 + x1 * x1;
#pragma unroll
        for (int o = 16; o > 0; o >>= 1) {
            s  += __shfl_xor_sync(0xffffffffu, s, o);
            s2 += __shfl_xor_sync(0xffffffffu, s2, o);
        }
        float mu  = s * (1.0f / 64.0f);
        float var = s2 * (1.0f / 64.0f) - mu * mu;
        float inv = rsqrtf(var + 1e-5f);
        float y0 = (x0 - mu) * inv * g0 + be0;
        float y1 = (x1 - mu) * inv * g1 + be1;
        out[(size_t)(row0 + r) * 64 + lane]      = fmaxf(y0, 0.0f);
        out[(size_t)(row0 + r) * 64 + lane + 32] = fmaxf(y1, 0.0f);
    }
}

// ============================================================
extern "C" void kernel_launch(void* const* d_in, const int* in_sizes, int n_in,
                              void* d_out, int out_size)
{
    (void)in_sizes; (void)n_in; (void)out_size;
    const float* L0 = (const float*)d_in[0];
    const float* W0 = (const float*)d_in[1];
    const float* b0 = (const float*)d_in[2];
    const float* L1 = (const float*)d_in[3];
    const float* W1 = (const float*)d_in[4];
    const float* b1 = (const float*)d_in[5];
    const float* L2 = (const float*)d_in[6];
    const float* W2 = (const float*)d_in[7];
    const float* b2 = (const float*)d_in[8];
    const float* corr  = (const float*)d_in[9];
    const float* Wb    = (const float*)d_in[10];
    const float* bb    = (const float*)d_in[11];
    const float* gamma = (const float*)d_in[12];
    const float* beta  = (const float*)d_in[13];
    float* out = (float*)d_out;

    cudaFuncSetAttribute(proj_mma_kernel, cudaFuncAttributeMaxDynamicSharedMemorySize, SMEM_PROJ);
    cudaFuncSetAttribute(ccsm_mma_kernel, cudaFuncAttributeMaxDynamicSharedMemorySize, SMEM_CS);
    cudaFuncSetAttribute(attfuse_mma_kernel, cudaFuncAttributeMaxDynamicSharedMemorySize, SMEM_AT);
    cudaFuncSetAttribute(final_mma_kernel, cudaFuncAttributeMaxDynamicSharedMemorySize, SMEM_FIN);

    prep_kernel<<<704, 256>>>(W0, W1, W2, Wb, corr);
    proj_mma_kernel<<<dim3(256, 3), 256, SMEM_PROJ>>>(L0, L1, L2, b0, b1, b2);
    ccsm_mma_kernel<<<dim3(512, 2), 256, SMEM_CS>>>();
    attfuse_mma_kernel<<<dim3(512, 4), 256, SMEM_AT>>>();
    final_mma_kernel<<<256, 256, SMEM_FIN>>>(bb, gamma, beta, out);
}